// round 3
// baseline (speedup 1.0000x reference)
#include <cuda_runtime.h>
#include <math.h>

#define Tt 256
#define Bb 8
#define Nn 128
#define Ee 512
#define Dd 80
#define Mm 512
#define Pp 256
#define G4 2048
#define NEGV -1e10f
#define EPSC 1e-4f
#define LOG2PI 1.8378770664093453f

// ---------------- device scratch (static, no allocation) ----------------
__device__ float g_W0T[96 * 256];        // prenet w0^T, zero-padded K 80->96
__device__ float g_W1PT[256 * 256];      // prenet w1^T
__device__ float g_WIHT[256 * 2048];     // lstm w_ih^T
__device__ float g_OW0ET[512 * 256];     // ow0[:, :E]^T
__device__ float g_OW0MT[512 * 256];     // ow0[:, E:]^T
__device__ float g_OW1T[256 * 256];      // ow1^T
__device__ float g_OW2TP[256 * 176];     // ow2^T zero-padded 161->176
__device__ float g_ob2p[176];
__device__ float g_bsum[2048];           // b_ih + b_hh
__device__ float g_ARX[2048 * 96];       // shifted mels, rows t*8+b, padded K
__device__ float g_PRE0[2048 * 256];
__device__ float g_PRE[2048 * 256];
__device__ float g_GI[2048 * 2048];      // gates input part + biases
__device__ float g_ZI[1024 * 256];       // inputs @ ow0E^T, rows b*128+n
__device__ float g_H[2048 * 512];        // h history, rows t*8+b
__device__ float g_HP[2048 * 256];       // H @ ow0M^T
__device__ float g_hping[2 * 4096];      // ping-pong h, layout [m*8+b]
__device__ float g_EM[2048 * 128];
__device__ float g_TV[2048 * 128];
__device__ int g_cnt;
__device__ int g_gen;

__device__ __forceinline__ float sigf(float x) { return 1.f / (1.f + __expf(-x)); }

__device__ __forceinline__ void gbar(int nb) {
    __threadfence();
    __syncthreads();
    if (threadIdx.x == 0) {
        int g = *((volatile int*)&g_gen);
        if (atomicAdd(&g_cnt, 1) == nb - 1) {
            g_cnt = 0;
            __threadfence();
            atomicAdd(&g_gen, 1);
        } else {
            while (*((volatile int*)&g_gen) == g) { __nanosleep(32); }
        }
    }
    __syncthreads();
}

// ---------------- prep: transposes / padding / shifted input ----------------
__global__ void k_prep(const float* __restrict__ w0, const float* __restrict__ w1p,
                       const float* __restrict__ wih, const float* __restrict__ ow0,
                       const float* __restrict__ ow1, const float* __restrict__ ow2,
                       const float* __restrict__ ob2, const float* __restrict__ bih,
                       const float* __restrict__ bhh, const float* __restrict__ mels) {
    int stride = gridDim.x * blockDim.x;
    int t0 = blockIdx.x * blockDim.x + threadIdx.x;
    for (int i = t0; i < 96 * 256; i += stride) {
        int k = i >> 8, p = i & 255;
        g_W0T[i] = (k < 80) ? w0[p * 80 + k] : 0.f;
    }
    for (int i = t0; i < 256 * 256; i += stride) {
        int k = i >> 8, p = i & 255;
        g_W1PT[i] = w1p[p * 256 + k];
    }
    for (int i = t0; i < 256 * 2048; i += stride) {
        int k = i >> 11, g = i & 2047;
        g_WIHT[i] = wih[g * 256 + k];
    }
    for (int i = t0; i < 512 * 256; i += stride) {
        int e = i >> 8, p = i & 255;
        g_OW0ET[i] = ow0[p * 1024 + e];
        g_OW0MT[i] = ow0[p * 1024 + 512 + e];
    }
    for (int i = t0; i < 256 * 256; i += stride) {
        int k = i >> 8, q = i & 255;
        g_OW1T[i] = ow1[q * 256 + k];
    }
    for (int i = t0; i < 256 * 176; i += stride) {
        int k = i / 176, r = i % 176;
        g_OW2TP[i] = (r < 161) ? ow2[r * 256 + k] : 0.f;
    }
    for (int i = t0; i < 176; i += stride) g_ob2p[i] = (i < 161) ? ob2[i] : 0.f;
    for (int i = t0; i < 2048; i += stride) g_bsum[i] = bih[i] + bhh[i];
    for (int i = t0; i < 2048 * 96; i += stride) {
        int row = i / 96, d = i % 96;
        int t = row >> 3, b = row & 7;
        g_ARX[i] = (d < 80 && t > 0) ? mels[(b * 80 + d) * 256 + (t - 1)] : 0.f;
    }
}

// ---------------- generic tiled SGEMM: C = act(A @ BT + bias) ----------------
// A: [R][K] row-major, BT: [K][C] row-major. Tile 64x128, TK=32, 256 threads.
template <int ACT>
__global__ __launch_bounds__(256) void k_gemm(float* __restrict__ Cm,
                                              const float* __restrict__ Am,
                                              const float* __restrict__ BT,
                                              const float* __restrict__ bias,
                                              int R, int Ccols, int K) {
    __shared__ __align__(16) float As[32 * 68];
    __shared__ __align__(16) float Bs[32 * 128];
    int row0 = blockIdx.y * 64, col0 = blockIdx.x * 128;
    int tid = threadIdx.x;
    int tr = tid >> 4, tc = tid & 15;
    int r0 = tr * 4, c0 = tc * 8;
    float acc[4][8] = {};
    for (int kt = 0; kt < K; kt += 32) {
        for (int i = tid; i < 2048; i += 256) {
            int r = i >> 5, k = i & 31;
            As[k * 68 + r] = Am[(row0 + r) * K + kt + k];
        }
        for (int i = tid; i < 4096; i += 256) {
            int k = i >> 7, c = i & 127;
            Bs[k * 128 + c] = BT[(kt + k) * Ccols + col0 + c];
        }
        __syncthreads();
#pragma unroll 8
        for (int k = 0; k < 32; k++) {
            float4 a4 = *(const float4*)&As[k * 68 + r0];
            float4 b0 = *(const float4*)&Bs[k * 128 + c0];
            float4 b1 = *(const float4*)&Bs[k * 128 + c0 + 4];
            float av[4] = {a4.x, a4.y, a4.z, a4.w};
            float bv[8] = {b0.x, b0.y, b0.z, b0.w, b1.x, b1.y, b1.z, b1.w};
#pragma unroll
            for (int ci = 0; ci < 8; ci++)
#pragma unroll
                for (int ri = 0; ri < 4; ri++)
                    acc[ri][ci] = fmaf(av[ri], bv[ci], acc[ri][ci]);
        }
        __syncthreads();
    }
#pragma unroll
    for (int ri = 0; ri < 4; ri++) {
        int r = row0 + r0 + ri;
#pragma unroll
        for (int ci = 0; ci < 8; ci++) {
            int c = col0 + c0 + ci;
            float v = acc[ri][ci] + (bias ? bias[c] : 0.f);
            if (ACT) v = fmaxf(v, 0.f);
            Cm[r * Ccols + c] = v;
        }
    }
}

// ---------------- persistent sequential LSTM ----------------
// 128 blocks x 256 threads; block bk owns m in [bk*4, bk*4+4).
__global__ __launch_bounds__(256) void k_lstm(const float* __restrict__ whh) {
    extern __shared__ __align__(16) float sm[];
    float* Wsl = sm;                 // 16*512
    float* hs = sm + 8192;           // 512*12 (padded, float4-aligned)
    float* gsm = sm + 8192 + 6144;   // 16*8
    int tid = threadIdx.x;
    int m0 = blockIdx.x * 4;
    for (int i = tid; i < 16 * 512; i += 256) {
        int mg = i >> 9, k = i & 511;
        int ml = mg >> 2, gate = mg & 3;
        Wsl[i] = whh[(gate * 512 + m0 + ml) * 512 + k];
    }
    if (tid < 32) {
        int ml = tid >> 3, b = tid & 7;
        g_hping[(m0 + ml) * 8 + b] = 0.f;
    }
    float c_reg = 0.f;
    int pair = tid >> 4, lane16 = tid & 15;
    gbar(128);
    for (int t = 0; t < Tt; t++) {
        int cur = t & 1, nxt = cur ^ 1;
        for (int i = tid; i < 4096; i += 256) {
            float v = __ldcg(&g_hping[cur * 4096 + i]);
            hs[(i >> 3) * 12 + (i & 7)] = v;
        }
        __syncthreads();
        float acc[8];
#pragma unroll
        for (int b = 0; b < 8; b++) acc[b] = 0.f;
        const float* wrow = &Wsl[pair * 512];
#pragma unroll 8
        for (int j = 0; j < 32; j++) {
            int k = lane16 + j * 16;
            float w = wrow[k];
            float4 hA = *(const float4*)&hs[k * 12];
            float4 hB = *(const float4*)&hs[k * 12 + 4];
            acc[0] = fmaf(w, hA.x, acc[0]);
            acc[1] = fmaf(w, hA.y, acc[1]);
            acc[2] = fmaf(w, hA.z, acc[2]);
            acc[3] = fmaf(w, hA.w, acc[3]);
            acc[4] = fmaf(w, hB.x, acc[4]);
            acc[5] = fmaf(w, hB.y, acc[5]);
            acc[6] = fmaf(w, hB.z, acc[6]);
            acc[7] = fmaf(w, hB.w, acc[7]);
        }
#pragma unroll
        for (int off = 8; off >= 1; off >>= 1)
#pragma unroll
            for (int b = 0; b < 8; b++)
                acc[b] += __shfl_down_sync(0xffffffffu, acc[b], off, 16);
        if (lane16 == 0) {
#pragma unroll
            for (int b = 0; b < 8; b++) gsm[pair * 8 + b] = acc[b];
        }
        __syncthreads();
        if (tid < 32) {
            int ml = tid >> 3, b = tid & 7;
            const float* gi = &g_GI[(t * 8 + b) * 2048];
            int m = m0 + ml;
            float ig = gsm[(ml * 4 + 0) * 8 + b] + gi[0 * 512 + m];
            float fg = gsm[(ml * 4 + 1) * 8 + b] + gi[1 * 512 + m];
            float gg = gsm[(ml * 4 + 2) * 8 + b] + gi[2 * 512 + m];
            float og = gsm[(ml * 4 + 3) * 8 + b] + gi[3 * 512 + m];
            float cn = sigf(fg) * c_reg + sigf(ig) * tanhf(gg);
            float h = sigf(og) * tanhf(cn);
            c_reg = cn;
            g_hping[nxt * 4096 + m * 8 + b] = h;
            g_H[(t * 8 + b) * 512 + m] = h;
        }
        gbar(128);
    }
}

// ---------------- fused A1->A2->P->emission per (t,b) ----------------
// smem floats: A1 64x260 | A2 64x260 | Ws 32x256 | Pm 64x176 | xt 96
#define SM_A1 0
#define SM_A2 16640
#define SM_WS 33280
#define SM_PM 41472
#define SM_XT 52736
#define EMIT_SMEMF 52832

__global__ __launch_bounds__(256) void k_emit(const float* __restrict__ mels,
                                              const float* __restrict__ ob0,
                                              const float* __restrict__ ob1,
                                              const int* __restrict__ inputs_len) {
    extern __shared__ __align__(16) float sm2[];
    float* A1 = sm2 + SM_A1;
    float* A2 = sm2 + SM_A2;
    float* Ws = sm2 + SM_WS;
    float* Pm = sm2 + SM_PM;
    float* xt = sm2 + SM_XT;
    int tb = blockIdx.x;
    int t = tb >> 3, b = tb & 7;
    int tid = threadIdx.x;
    if (tid < 80) xt[tid] = mels[(b * 80 + tid) * 256 + t];
    float hp = g_HP[tb * 256 + tid] + ob0[tid];
    int ilen = inputs_len[b];
    int tr = tid >> 4, tc = tid & 15;
    int r0 = tr * 4;

    for (int half = 0; half < 2; half++) {
        int n0 = half * 64;
        __syncthreads();
        // stage A1 = relu(ZI + h@ow0M + ob0)
        for (int i = 0; i < 64; i++) {
            float z = g_ZI[(b * 128 + n0 + i) * 256 + tid];
            A1[i * 260 + tid] = fmaxf(z + hp, 0.f);
        }
        __syncthreads();
        // GEMM2: A2 = relu(A1 @ OW1T + ob1), 64x256, K=256
        {
            int c0 = tc * 16;
            float acc[4][16] = {};
            for (int kt = 0; kt < 256; kt += 32) {
                for (int i = tid; i < 8192; i += 256)
                    Ws[i] = g_OW1T[(kt + (i >> 8)) * 256 + (i & 255)];
                __syncthreads();
#pragma unroll 4
                for (int k = 0; k < 32; k++) {
                    float a[4];
#pragma unroll
                    for (int ri = 0; ri < 4; ri++) a[ri] = A1[(r0 + ri) * 260 + kt + k];
                    float4 w0 = *(const float4*)&Ws[k * 256 + c0];
                    float4 w1 = *(const float4*)&Ws[k * 256 + c0 + 4];
                    float4 w2 = *(const float4*)&Ws[k * 256 + c0 + 8];
                    float4 w3 = *(const float4*)&Ws[k * 256 + c0 + 12];
                    float w[16] = {w0.x, w0.y, w0.z, w0.w, w1.x, w1.y, w1.z, w1.w,
                                   w2.x, w2.y, w2.z, w2.w, w3.x, w3.y, w3.z, w3.w};
#pragma unroll
                    for (int ci = 0; ci < 16; ci++)
#pragma unroll
                        for (int ri = 0; ri < 4; ri++)
                            acc[ri][ci] = fmaf(a[ri], w[ci], acc[ri][ci]);
                }
                __syncthreads();
            }
#pragma unroll
            for (int ri = 0; ri < 4; ri++)
#pragma unroll
                for (int ci = 0; ci < 16; ci++)
                    A2[(r0 + ri) * 260 + c0 + ci] =
                        fmaxf(acc[ri][ci] + ob1[c0 + ci], 0.f);
        }
        __syncthreads();
        // GEMM3: Pm = A2 @ OW2TP + ob2p, 64x176, K=256
        {
            int c3 = tc * 11;
            float pcc[4][11] = {};
            for (int kt = 0; kt < 256; kt += 32) {
                for (int i = tid; i < 32 * 176; i += 256)
                    Ws[i] = g_OW2TP[kt * 176 + i];
                __syncthreads();
#pragma unroll 4
                for (int k = 0; k < 32; k++) {
                    float a[4];
#pragma unroll
                    for (int ri = 0; ri < 4; ri++) a[ri] = A2[(r0 + ri) * 260 + kt + k];
#pragma unroll
                    for (int ci = 0; ci < 11; ci++) {
                        float w = Ws[k * 176 + c3 + ci];
#pragma unroll
                        for (int ri = 0; ri < 4; ri++)
                            pcc[ri][ci] = fmaf(a[ri], w, pcc[ri][ci]);
                    }
                }
                __syncthreads();
            }
#pragma unroll
            for (int ri = 0; ri < 4; ri++)
#pragma unroll
                for (int ci = 0; ci < 11; ci++)
                    Pm[(r0 + ri) * 176 + c3 + ci] = pcc[ri][ci] + g_ob2p[c3 + ci];
        }
        __syncthreads();
        // emission: em[n] = sum_d(-0.5 z^2 - log std) - 40*log2pi, masked
        {
            int row = tid >> 2, q = tid & 3;
            float accv = 0.f;
            for (int d = q * 20; d < q * 20 + 20; d++) {
                float mean = Pm[row * 176 + d];
                float sh = Pm[row * 176 + 80 + d];
                float sp = (sh > 15.f) ? sh : __logf(1.f + __expf(sh));
                float stdv = sp + 0.001f;
                float z = (xt[d] - mean) / stdv;
                accv += -0.5f * z * z - __logf(stdv);
            }
            accv += __shfl_down_sync(0xffffffffu, accv, 2, 4);
            accv += __shfl_down_sync(0xffffffffu, accv, 1, 4);
            if (q == 0) {
                int n = n0 + row;
                float em = accv - 40.f * LOG2PI;
                em = (n < ilen) ? em : 0.f;
                g_EM[tb * 128 + n] = em;
                g_TV[tb * 128 + n] = Pm[row * 176 + 160];
            }
        }
        __syncthreads();
    }
}

// ---------------- alpha recursion (per-batch independent) ----------------
__global__ __launch_bounds__(128) void k_alpha(float* __restrict__ out,
                                               const int* __restrict__ inputs_len,
                                               const int* __restrict__ mel_lens) {
    __shared__ float la_s[128];
    __shared__ float red[8];
    int b = blockIdx.x, n = threadIdx.x;
    int wid = n >> 5, lane = n & 31;
    bool maskn = n < inputs_len[b];
    int mlen = mel_lens[b];
    float la_prev = 0.f;
    float lp = 0.f;
    for (int t = 0; t < Tt; t++) {
        int tb = t * 8 + b;
        float em = g_EM[tb * 128 + n];
        float v;
        if (t == 0) {
            v = ((n == 0) ? 0.f : NEGV) + em;
        } else {
            float tv = g_TV[tb * 128 + n];
            float stay = la_prev + __logf(fmaxf(1.f / (1.f + __expf(tv)), EPSC));
            float leave;
            if (n == 0) {
                leave = NEGV;
            } else {
                float tvm = g_TV[tb * 128 + n - 1];
                leave = la_s[n - 1] +
                        __logf(fmaxf(1.f / (1.f + __expf(-tvm)), EPSC));
            }
            float mx = fmaxf(stay, leave), mn = fminf(stay, leave);
            float ladd = mx + log1pf(__expf(mn - mx));
            v = em + (maskn ? ladd : NEGV);
        }
        __syncthreads();
        float m = v;
#pragma unroll
        for (int off = 16; off; off >>= 1)
            m = fmaxf(m, __shfl_xor_sync(0xffffffffu, m, off));
        if (lane == 0) red[wid] = m;
        __syncthreads();
        m = fmaxf(fmaxf(red[0], red[1]), fmaxf(red[2], red[3]));
        float e = __expf(v - m);
        float s = e;
#pragma unroll
        for (int off = 16; off; off >>= 1)
            s += __shfl_xor_sync(0xffffffffu, s, off);
        if (lane == 0) red[4 + wid] = s;
        __syncthreads();
        s = red[4] + red[5] + red[6] + red[7];
        float logc = m + __logf(s);
        float la = v - logc;
        out[8 + (b * 256 + t) * 128 + n] = la;
        la_s[n] = la;
        la_prev = la;
        if (n == 0 && t < mlen) lp += logc;
        __syncthreads();
    }
    if (n == 0) out[b] = lp;
}

// ---------------- launch ----------------
extern "C" void kernel_launch(void* const* d_in, const int* in_sizes, int n_in,
                              void* d_out, int out_size) {
    const float* inputs = (const float*)d_in[0];
    const float* mels = (const float*)d_in[1];
    const float* w0 = (const float*)d_in[2];
    const float* w1p = (const float*)d_in[3];
    const float* wih = (const float*)d_in[4];
    const float* whh = (const float*)d_in[5];
    const float* bih = (const float*)d_in[6];
    const float* bhh = (const float*)d_in[7];
    const float* ow0 = (const float*)d_in[8];
    const float* ob0 = (const float*)d_in[9];
    const float* ow1 = (const float*)d_in[10];
    const float* ob1 = (const float*)d_in[11];
    const float* ow2 = (const float*)d_in[12];
    const float* ob2 = (const float*)d_in[13];
    const int* inputs_len = (const int*)d_in[14];
    const int* mel_lens = (const int*)d_in[15];
    float* out = (float*)d_out;

    cudaFuncSetAttribute(k_lstm, cudaFuncAttributeMaxDynamicSharedMemorySize,
                         (8192 + 6144 + 128) * 4);
    cudaFuncSetAttribute(k_emit, cudaFuncAttributeMaxDynamicSharedMemorySize,
                         EMIT_SMEMF * 4);

    float* pre0;  cudaGetSymbolAddress((void**)&pre0, g_PRE0);
    float* pre;   cudaGetSymbolAddress((void**)&pre, g_PRE);
    float* gi;    cudaGetSymbolAddress((void**)&gi, g_GI);
    float* zi;    cudaGetSymbolAddress((void**)&zi, g_ZI);
    float* hh;    cudaGetSymbolAddress((void**)&hh, g_H);
    float* hpm;   cudaGetSymbolAddress((void**)&hpm, g_HP);
    float* arx;   cudaGetSymbolAddress((void**)&arx, g_ARX);
    float* w0t;   cudaGetSymbolAddress((void**)&w0t, g_W0T);
    float* w1pt;  cudaGetSymbolAddress((void**)&w1pt, g_W1PT);
    float* wiht;  cudaGetSymbolAddress((void**)&wiht, g_WIHT);
    float* ow0et; cudaGetSymbolAddress((void**)&ow0et, g_OW0ET);
    float* ow0mt; cudaGetSymbolAddress((void**)&ow0mt, g_OW0MT);
    float* bsum;  cudaGetSymbolAddress((void**)&bsum, g_bsum);

    k_prep<<<256, 256>>>(w0, w1p, wih, ow0, ow1, ow2, ob2, bih, bhh, mels);
    k_gemm<1><<<dim3(2, 32), 256>>>(pre0, arx, w0t, nullptr, 2048, 256, 96);
    k_gemm<1><<<dim3(2, 32), 256>>>(pre, pre0, w1pt, nullptr, 2048, 256, 256);
    k_gemm<0><<<dim3(16, 32), 256>>>(gi, pre, wiht, bsum, 2048, 2048, 256);
    k_gemm<0><<<dim3(2, 16), 256>>>(zi, inputs, ow0et, nullptr, 1024, 256, 512);
    k_lstm<<<128, 256, (8192 + 6144 + 128) * 4>>>(whh);
    k_gemm<0><<<dim3(2, 32), 256>>>(hpm, hh, ow0mt, nullptr, 2048, 256, 512);
    k_emit<<<2048, 256, EMIT_SMEMF * 4>>>(mels, ob0, ob1, inputs_len);
    k_alpha<<<8, 128>>>(out, inputs_len, mel_lens);
    (void)in_sizes; (void)n_in; (void)out_size;
}

// round 4
// speedup vs baseline: 1.5415x; 1.5415x over previous
#include <cuda_runtime.h>
#include <math.h>

#define Tt 256
#define NEGV -1e10f
#define EPSC 1e-4f
#define LOG2PI 1.8378770664093453f

typedef unsigned long long ull;

#define PACK2(out, x) asm("mov.b64 %0, {%1, %1};" : "=l"(out) : "r"(__float_as_uint(x)))
#define UNPK(lo, hi, in) { unsigned int ulo, uhi; \
    asm("mov.b64 {%0, %1}, %2;" : "=r"(ulo), "=r"(uhi) : "l"(in)); \
    lo = __uint_as_float(ulo); hi = __uint_as_float(uhi); }
#define FMA2(d, a, b) asm("fma.rn.f32x2 %0, %1, %2, %0;" : "+l"(d) : "l"(a), "l"(b))

// ---------------- device scratch ----------------
__device__ float g_W0T[96 * 256];
__device__ float g_W1PT[256 * 256];
__device__ float g_WIHT[256 * 2048];
__device__ float g_OW0ET[512 * 256];
__device__ float g_OW0MT[512 * 256];
__device__ float g_OW1T[256 * 256];
__device__ float g_OW2TP[256 * 192];     // ow2^T zero-padded cols 161->192
__device__ float g_ob2p[192];
__device__ float g_bsum[2048];
__device__ float g_ARX[2048 * 96];
__device__ float g_PRE0[2048 * 256];
__device__ float g_PRE[2048 * 256];
__device__ float g_GI[2048 * 2048];
__device__ float g_ZI[1024 * 256];
__device__ float g_H[2048 * 512];
__device__ float g_HP[2048 * 256];       // H @ ow0M^T + ob0
__device__ float g_hping[2 * 4096];
__device__ float g_A2[262144 * 256];     // relu(A1 @ ow1^T + ob1)
__device__ float g_EM[2048 * 128];
__device__ float g_LS[2048 * 128];       // log stay
__device__ float g_LM[2048 * 128];       // log move
__device__ int g_done[257 * 8 * 32];     // barrier counters, 128B stride

__device__ __forceinline__ float sigf(float x) { return 1.f / (1.f + __expf(-x)); }

// ---------------- prep ----------------
__global__ void k_prep(const float* __restrict__ w0, const float* __restrict__ w1p,
                       const float* __restrict__ wih, const float* __restrict__ ow0,
                       const float* __restrict__ ow1, const float* __restrict__ ow2,
                       const float* __restrict__ ob2, const float* __restrict__ bih,
                       const float* __restrict__ bhh, const float* __restrict__ mels) {
    int stride = gridDim.x * blockDim.x;
    int t0 = blockIdx.x * blockDim.x + threadIdx.x;
    for (int i = t0; i < 96 * 256; i += stride) {
        int k = i >> 8, p = i & 255;
        g_W0T[i] = (k < 80) ? w0[p * 80 + k] : 0.f;
    }
    for (int i = t0; i < 256 * 256; i += stride) {
        int k = i >> 8, p = i & 255;
        g_W1PT[i] = w1p[p * 256 + k];
    }
    for (int i = t0; i < 256 * 2048; i += stride) {
        int k = i >> 11, g = i & 2047;
        g_WIHT[i] = wih[g * 256 + k];
    }
    for (int i = t0; i < 512 * 256; i += stride) {
        int e = i >> 8, p = i & 255;
        g_OW0ET[i] = ow0[p * 1024 + e];
        g_OW0MT[i] = ow0[p * 1024 + 512 + e];
    }
    for (int i = t0; i < 256 * 256; i += stride) {
        int k = i >> 8, q = i & 255;
        g_OW1T[i] = ow1[q * 256 + k];
    }
    for (int i = t0; i < 256 * 192; i += stride) {
        int k = i / 192, r = i % 192;
        g_OW2TP[i] = (r < 161) ? ow2[r * 256 + k] : 0.f;
    }
    for (int i = t0; i < 192; i += stride) g_ob2p[i] = (i < 161) ? ob2[i] : 0.f;
    for (int i = t0; i < 2048; i += stride) g_bsum[i] = bih[i] + bhh[i];
    for (int i = t0; i < 2048 * 96; i += stride) {
        int row = i / 96, d = i % 96;
        int t = row >> 3, b = row & 7;
        g_ARX[i] = (d < 80 && t > 0) ? mels[(b * 80 + d) * 256 + (t - 1)] : 0.f;
    }
    for (int i = t0; i < 257 * 8 * 32; i += stride) g_done[i] = 0;
}

// ---------------- generic tiled SGEMM (small matrices) ----------------
template <int ACT>
__global__ __launch_bounds__(256) void k_gemm(float* __restrict__ Cm,
                                              const float* __restrict__ Am,
                                              const float* __restrict__ BT,
                                              const float* __restrict__ bias,
                                              int R, int Ccols, int K) {
    __shared__ __align__(16) float As[32 * 68];
    __shared__ __align__(16) float Bs[32 * 128];
    int row0 = blockIdx.y * 64, col0 = blockIdx.x * 128;
    int tid = threadIdx.x;
    int tr = tid >> 4, tc = tid & 15;
    int r0 = tr * 4, c0 = tc * 8;
    float acc[4][8] = {};
    for (int kt = 0; kt < K; kt += 32) {
        for (int i = tid; i < 2048; i += 256) {
            int r = i >> 5, k = i & 31;
            As[k * 68 + r] = Am[(row0 + r) * K + kt + k];
        }
        for (int i = tid; i < 4096; i += 256) {
            int k = i >> 7, c = i & 127;
            Bs[k * 128 + c] = BT[(kt + k) * Ccols + col0 + c];
        }
        __syncthreads();
#pragma unroll 8
        for (int k = 0; k < 32; k++) {
            float4 a4 = *(const float4*)&As[k * 68 + r0];
            float4 b0 = *(const float4*)&Bs[k * 128 + c0];
            float4 b1 = *(const float4*)&Bs[k * 128 + c0 + 4];
            float av[4] = {a4.x, a4.y, a4.z, a4.w};
            float bv[8] = {b0.x, b0.y, b0.z, b0.w, b1.x, b1.y, b1.z, b1.w};
#pragma unroll
            for (int ci = 0; ci < 8; ci++)
#pragma unroll
                for (int ri = 0; ri < 4; ri++)
                    acc[ri][ci] = fmaf(av[ri], bv[ci], acc[ri][ci]);
        }
        __syncthreads();
    }
#pragma unroll
    for (int ri = 0; ri < 4; ri++) {
        int r = row0 + r0 + ri;
#pragma unroll
        for (int ci = 0; ci < 8; ci++) {
            int c = col0 + c0 + ci;
            float v = acc[ri][ci] + (bias ? bias[c] : 0.f);
            if (ACT) v = fmaxf(v, 0.f);
            Cm[r * Ccols + c] = v;
        }
    }
}

// ---------------- LSTM grid barrier (8-way split counters) ----------------
__device__ __forceinline__ void lstm_bar(int slot, int grp) {
    __syncthreads();
    if (threadIdx.x == 0) {
        __threadfence();
        atomicAdd(&g_done[(slot * 8 + grp) * 32], 1);
        for (;;) {
            int s = 0;
#pragma unroll
            for (int j = 0; j < 8; j++)
                s += *((volatile int*)&g_done[(slot * 8 + j) * 32]);
            if (s == 128) break;
            __nanosleep(32);
        }
        __threadfence();
    }
    __syncthreads();
}

// ---------------- persistent sequential LSTM ----------------
__global__ __launch_bounds__(256) void k_lstm(const float* __restrict__ whh) {
    extern __shared__ __align__(16) float sm[];
    float* Wsl = sm;                 // 16*512
    float* hs = sm + 8192;           // 512*12
    float* gsm = sm + 8192 + 6144;   // 16*8
    int tid = threadIdx.x;
    int m0 = blockIdx.x * 4;
    int grp = blockIdx.x & 7;
    for (int i = tid; i < 16 * 512; i += 256) {
        int mg = i >> 9, k = i & 511;
        int ml = mg >> 2, gate = mg & 3;
        Wsl[i] = whh[(gate * 512 + m0 + ml) * 512 + k];
    }
    if (tid < 32) {
        int ml = tid >> 3, b = tid & 7;
        __stcg(&g_hping[(m0 + ml) * 8 + b], 0.f);
    }
    float c_reg = 0.f;
    int pair = tid >> 4, lane16 = tid & 15;
    lstm_bar(0, grp);
    for (int t = 0; t < Tt; t++) {
        int cur = t & 1, nxt = cur ^ 1;
        for (int i = tid; i < 4096; i += 256) {
            float v = __ldcg(&g_hping[cur * 4096 + i]);
            hs[(i >> 3) * 12 + (i & 7)] = v;
        }
        __syncthreads();
        float acc[8];
#pragma unroll
        for (int b = 0; b < 8; b++) acc[b] = 0.f;
        const float* wrow = &Wsl[pair * 512];
#pragma unroll 8
        for (int j = 0; j < 32; j++) {
            int k = lane16 + j * 16;
            float w = wrow[k];
            float4 hA = *(const float4*)&hs[k * 12];
            float4 hB = *(const float4*)&hs[k * 12 + 4];
            acc[0] = fmaf(w, hA.x, acc[0]);
            acc[1] = fmaf(w, hA.y, acc[1]);
            acc[2] = fmaf(w, hA.z, acc[2]);
            acc[3] = fmaf(w, hA.w, acc[3]);
            acc[4] = fmaf(w, hB.x, acc[4]);
            acc[5] = fmaf(w, hB.y, acc[5]);
            acc[6] = fmaf(w, hB.z, acc[6]);
            acc[7] = fmaf(w, hB.w, acc[7]);
        }
#pragma unroll
        for (int off = 8; off >= 1; off >>= 1)
#pragma unroll
            for (int b = 0; b < 8; b++)
                acc[b] += __shfl_down_sync(0xffffffffu, acc[b], off, 16);
        if (lane16 == 0) {
#pragma unroll
            for (int b = 0; b < 8; b++) gsm[pair * 8 + b] = acc[b];
        }
        __syncthreads();
        if (tid < 32) {
            int ml = tid >> 3, b = tid & 7;
            const float* gi = &g_GI[(t * 8 + b) * 2048];
            int m = m0 + ml;
            float ig = gsm[(ml * 4 + 0) * 8 + b] + gi[0 * 512 + m];
            float fg = gsm[(ml * 4 + 1) * 8 + b] + gi[1 * 512 + m];
            float gg = gsm[(ml * 4 + 2) * 8 + b] + gi[2 * 512 + m];
            float og = gsm[(ml * 4 + 3) * 8 + b] + gi[3 * 512 + m];
            float cn = sigf(fg) * c_reg + sigf(ig) * tanhf(gg);
            float h = sigf(og) * tanhf(cn);
            c_reg = cn;
            __stcg(&g_hping[nxt * 4096 + m * 8 + b], h);
            g_H[(t * 8 + b) * 512 + m] = h;
        }
        lstm_bar(t + 1, grp);
    }
}

// ---------------- GEMM2: A2 = relu(A1 @ OW1T + ob1), f32x2 packed ----------------
// A1 built on the fly: A1[row][k] = relu(ZI[(b*128+n)*256+k] + HP[tb*256+k])
// row = tb*128 + n; 128-row tile == one tb. Tile 128x128, K=256.
__global__ __launch_bounds__(256, 2) void k_g2(const float* __restrict__ ob1) {
    __shared__ __align__(16) float As[32 * 136];
    __shared__ __align__(16) float Bs[32 * 128];
    int tb = blockIdx.y;
    int b = tb & 7;
    int col0 = blockIdx.x * 128;
    int tid = threadIdx.x;
    int tr = tid >> 4, tc = tid & 15;
    int r0 = tr * 8, c0 = tc * 8;
    ull acc[4][8];
#pragma unroll
    for (int p = 0; p < 4; p++)
#pragma unroll
        for (int c = 0; c < 8; c++) acc[p][c] = 0ull;
    for (int kt = 0; kt < 256; kt += 32) {
        for (int i = tid; i < 4096; i += 256) {
            int k = i & 31, r = i >> 5;
            float z = g_ZI[((b << 7) + r) * 256 + kt + k] + g_HP[tb * 256 + kt + k];
            As[k * 136 + r] = fmaxf(z, 0.f);
        }
        for (int i = tid; i < 4096; i += 256) {
            int c = i & 127, k = i >> 7;
            Bs[k * 128 + c] = g_OW1T[(kt + k) * 256 + col0 + c];
        }
        __syncthreads();
#pragma unroll 8
        for (int k = 0; k < 32; k++) {
            ulonglong2 aA = *(const ulonglong2*)&As[k * 136 + r0];
            ulonglong2 aB = *(const ulonglong2*)&As[k * 136 + r0 + 4];
            float4 w0 = *(const float4*)&Bs[k * 128 + c0];
            float4 w1 = *(const float4*)&Bs[k * 128 + c0 + 4];
            float wf[8] = {w0.x, w0.y, w0.z, w0.w, w1.x, w1.y, w1.z, w1.w};
#pragma unroll
            for (int c = 0; c < 8; c++) {
                ull wp;
                PACK2(wp, wf[c]);
                FMA2(acc[0][c], aA.x, wp);
                FMA2(acc[1][c], aA.y, wp);
                FMA2(acc[2][c], aB.x, wp);
                FMA2(acc[3][c], aB.y, wp);
            }
        }
        __syncthreads();
    }
    int rowb = tb * 128 + r0;
#pragma unroll
    for (int p = 0; p < 4; p++) {
        float lo[8], hi[8];
#pragma unroll
        for (int c = 0; c < 8; c++) {
            UNPK(lo[c], hi[c], acc[p][c]);
            float bb = ob1[col0 + c0 + c];
            lo[c] = fmaxf(lo[c] + bb, 0.f);
            hi[c] = fmaxf(hi[c] + bb, 0.f);
        }
        float* d0 = &g_A2[(rowb + 2 * p) * 256 + col0 + c0];
        float* d1 = &g_A2[(rowb + 2 * p + 1) * 256 + col0 + c0];
        *(float4*)d0 = make_float4(lo[0], lo[1], lo[2], lo[3]);
        *(float4*)(d0 + 4) = make_float4(lo[4], lo[5], lo[6], lo[7]);
        *(float4*)d1 = make_float4(hi[0], hi[1], hi[2], hi[3]);
        *(float4*)(d1 + 4) = make_float4(hi[4], hi[5], hi[6], hi[7]);
    }
}

// ---------------- GEMM3 + emission fused, f32x2 packed ----------------
// P(64x192) = A2_tile(64x256) @ OW2TP(256x192) + ob2p, then emission epilogue.
#define G3_AS 0
#define G3_WS 2304
#define G3_PM 8448
#define G3_XT 20736
#define G3_SMEMF 20832

__global__ __launch_bounds__(256, 2) void k_g3em(const float* __restrict__ mels,
                                                 const int* __restrict__ inputs_len) {
    extern __shared__ __align__(16) float sm3[];
    float* As = sm3 + G3_AS;   // 32 x 72
    float* Ws = sm3 + G3_WS;   // 32 x 192
    float* Pm = sm3 + G3_PM;   // 64 x 192
    float* xt = sm3 + G3_XT;   // 96
    int bid = blockIdx.x;
    int tb = bid >> 1, half = bid & 1;
    int t = tb >> 3, b = tb & 7;
    int rowbase = tb * 128 + half * 64;
    int tid = threadIdx.x;
    if (tid < 80) xt[tid] = mels[(b * 80 + tid) * 256 + t];
    int tr = tid >> 4, tc = tid & 15;
    int r0 = tr * 4, c0 = tc * 12;
    ull acc[4][6];
#pragma unroll
    for (int ri = 0; ri < 4; ri++)
#pragma unroll
        for (int cj = 0; cj < 6; cj++) acc[ri][cj] = 0ull;
    for (int kt = 0; kt < 256; kt += 32) {
        for (int i = tid; i < 2048; i += 256) {
            int k = i & 31, r = i >> 5;
            As[k * 72 + r] = g_A2[(rowbase + r) * 256 + kt + k];
        }
        for (int i = tid; i < 1536; i += 256)
            ((float4*)Ws)[i] = ((const float4*)(g_OW2TP + kt * 192))[i];
        __syncthreads();
#pragma unroll 8
        for (int k = 0; k < 32; k++) {
            float4 av = *(const float4*)&As[k * 72 + r0];
            ull ap[4];
            PACK2(ap[0], av.x);
            PACK2(ap[1], av.y);
            PACK2(ap[2], av.z);
            PACK2(ap[3], av.w);
            ulonglong2 wA = *(const ulonglong2*)&Ws[k * 192 + c0];
            ulonglong2 wB = *(const ulonglong2*)&Ws[k * 192 + c0 + 4];
            ulonglong2 wC = *(const ulonglong2*)&Ws[k * 192 + c0 + 8];
            ull wv[6] = {wA.x, wA.y, wB.x, wB.y, wC.x, wC.y};
#pragma unroll
            for (int cj = 0; cj < 6; cj++) {
                FMA2(acc[0][cj], ap[0], wv[cj]);
                FMA2(acc[1][cj], ap[1], wv[cj]);
                FMA2(acc[2][cj], ap[2], wv[cj]);
                FMA2(acc[3][cj], ap[3], wv[cj]);
            }
        }
        __syncthreads();
    }
#pragma unroll
    for (int ri = 0; ri < 4; ri++)
#pragma unroll
        for (int cj = 0; cj < 6; cj++) {
            float lo, hi;
            UNPK(lo, hi, acc[ri][cj]);
            int col = c0 + 2 * cj;
            Pm[(r0 + ri) * 192 + col] = lo + g_ob2p[col];
            Pm[(r0 + ri) * 192 + col + 1] = hi + g_ob2p[col + 1];
        }
    __syncthreads();
    // emission + transition-term precompute
    {
        int row = tid >> 2, q = tid & 3;
        int ilen = inputs_len[b];
        float accv = 0.f;
        for (int d = q * 20; d < q * 20 + 20; d++) {
            float mean = Pm[row * 192 + d];
            float sh = Pm[row * 192 + 80 + d];
            float sp = (sh > 15.f) ? sh : __logf(1.f + __expf(sh));
            float stdv = sp + 0.001f;
            float z = (xt[d] - mean) / stdv;
            accv += -0.5f * z * z - __logf(stdv);
        }
        accv += __shfl_down_sync(0xffffffffu, accv, 2, 4);
        accv += __shfl_down_sync(0xffffffffu, accv, 1, 4);
        if (q == 0) {
            int n = half * 64 + row;
            float em = accv - 40.f * LOG2PI;
            g_EM[tb * 128 + n] = (n < ilen) ? em : 0.f;
            float tv = Pm[row * 192 + 160];
            float s_move = 1.f / (1.f + __expf(-tv));
            float s_stay = 1.f - s_move;
            g_LS[tb * 128 + n] = __logf(fmaxf(s_stay, EPSC));
            g_LM[tb * 128 + n] = __logf(fmaxf(s_move, EPSC));
        }
    }
}

// ---------------- alpha recursion ----------------
__global__ __launch_bounds__(128) void k_alpha(float* __restrict__ out,
                                               const int* __restrict__ inputs_len,
                                               const int* __restrict__ mel_lens) {
    __shared__ float la_s[128];
    __shared__ float red[8];
    int b = blockIdx.x, n = threadIdx.x;
    int wid = n >> 5, lane = n & 31;
    bool maskn = n < inputs_len[b];
    int mlen = mel_lens[b];
    float la_prev = 0.f;
    float lp = 0.f;
    for (int t = 0; t < Tt; t++) {
        int tb = t * 8 + b;
        float em = g_EM[tb * 128 + n];
        float v;
        if (t == 0) {
            v = ((n == 0) ? 0.f : NEGV) + em;
        } else {
            float stay = la_prev + g_LS[tb * 128 + n];
            float leave = (n == 0) ? NEGV
                                   : la_s[n - 1] + g_LM[tb * 128 + n - 1];
            float mx = fmaxf(stay, leave), mn = fminf(stay, leave);
            float ladd = mx + log1pf(__expf(mn - mx));
            v = em + (maskn ? ladd : NEGV);
        }
        __syncthreads();
        float m = v;
#pragma unroll
        for (int off = 16; off; off >>= 1)
            m = fmaxf(m, __shfl_xor_sync(0xffffffffu, m, off));
        if (lane == 0) red[wid] = m;
        __syncthreads();
        m = fmaxf(fmaxf(red[0], red[1]), fmaxf(red[2], red[3]));
        float e = __expf(v - m);
        float s = e;
#pragma unroll
        for (int off = 16; off; off >>= 1)
            s += __shfl_xor_sync(0xffffffffu, s, off);
        if (lane == 0) red[4 + wid] = s;
        __syncthreads();
        s = red[4] + red[5] + red[6] + red[7];
        float logc = m + __logf(s);
        float la = v - logc;
        out[8 + (b * 256 + t) * 128 + n] = la;
        la_s[n] = la;
        la_prev = la;
        if (n == 0 && t < mlen) lp += logc;
        __syncthreads();
    }
    if (n == 0) out[b] = lp;
}

// ---------------- launch ----------------
extern "C" void kernel_launch(void* const* d_in, const int* in_sizes, int n_in,
                              void* d_out, int out_size) {
    const float* inputs = (const float*)d_in[0];
    const float* mels = (const float*)d_in[1];
    const float* w0 = (const float*)d_in[2];
    const float* w1p = (const float*)d_in[3];
    const float* wih = (const float*)d_in[4];
    const float* whh = (const float*)d_in[5];
    const float* bih = (const float*)d_in[6];
    const float* bhh = (const float*)d_in[7];
    const float* ow0 = (const float*)d_in[8];
    const float* ob0 = (const float*)d_in[9];
    const float* ow1 = (const float*)d_in[10];
    const float* ob1 = (const float*)d_in[11];
    const float* ow2 = (const float*)d_in[12];
    const float* ob2 = (const float*)d_in[13];
    const int* inputs_len = (const int*)d_in[14];
    const int* mel_lens = (const int*)d_in[15];
    float* out = (float*)d_out;

    cudaFuncSetAttribute(k_lstm, cudaFuncAttributeMaxDynamicSharedMemorySize,
                         (8192 + 6144 + 128) * 4);
    cudaFuncSetAttribute(k_g3em, cudaFuncAttributeMaxDynamicSharedMemorySize,
                         G3_SMEMF * 4);

    float* pre0;  cudaGetSymbolAddress((void**)&pre0, g_PRE0);
    float* pre;   cudaGetSymbolAddress((void**)&pre, g_PRE);
    float* gi;    cudaGetSymbolAddress((void**)&gi, g_GI);
    float* zi;    cudaGetSymbolAddress((void**)&zi, g_ZI);
    float* hh;    cudaGetSymbolAddress((void**)&hh, g_H);
    float* hpm;   cudaGetSymbolAddress((void**)&hpm, g_HP);
    float* arx;   cudaGetSymbolAddress((void**)&arx, g_ARX);
    float* w0t;   cudaGetSymbolAddress((void**)&w0t, g_W0T);
    float* w1pt;  cudaGetSymbolAddress((void**)&w1pt, g_W1PT);
    float* wiht;  cudaGetSymbolAddress((void**)&wiht, g_WIHT);
    float* ow0et; cudaGetSymbolAddress((void**)&ow0et, g_OW0ET);
    float* ow0mt; cudaGetSymbolAddress((void**)&ow0mt, g_OW0MT);
    float* bsum;  cudaGetSymbolAddress((void**)&bsum, g_bsum);

    k_prep<<<256, 256>>>(w0, w1p, wih, ow0, ow1, ow2, ob2, bih, bhh, mels);
    k_gemm<1><<<dim3(2, 32), 256>>>(pre0, arx, w0t, nullptr, 2048, 256, 96);
    k_gemm<1><<<dim3(2, 32), 256>>>(pre, pre0, w1pt, nullptr, 2048, 256, 256);
    k_gemm<0><<<dim3(16, 32), 256>>>(gi, pre, wiht, bsum, 2048, 2048, 256);
    k_gemm<0><<<dim3(2, 16), 256>>>(zi, inputs, ow0et, nullptr, 1024, 256, 512);
    k_lstm<<<128, 256, (8192 + 6144 + 128) * 4>>>(whh);
    k_gemm<0><<<dim3(2, 32), 256>>>(hpm, hh, ow0mt, ob0, 2048, 256, 512);
    k_g2<<<dim3(2, 2048), 256>>>(ob1);
    k_g3em<<<4096, 256, G3_SMEMF * 4>>>(mels, inputs_len);
    k_alpha<<<8, 128>>>(out, inputs_len, mel_lens);
    (void)in_sizes; (void)n_in; (void)out_size;
}

// round 5
// speedup vs baseline: 1.6246x; 1.0540x over previous
#include <cuda_runtime.h>
#include <math.h>

#define Tt 256
#define NEGV -1e10f
#define EPSC 1e-4f
#define LOG2PI 1.8378770664093453f

typedef unsigned long long ull;

#define PACK2(out, x) asm("mov.b64 %0, {%1, %1};" : "=l"(out) : "r"(__float_as_uint(x)))
#define UNPK(lo, hi, in) { unsigned int ulo, uhi; \
    asm("mov.b64 {%0, %1}, %2;" : "=r"(ulo), "=r"(uhi) : "l"(in)); \
    lo = __uint_as_float(ulo); hi = __uint_as_float(uhi); }
#define FMA2(d, a, b) asm("fma.rn.f32x2 %0, %1, %2, %0;" : "+l"(d) : "l"(a), "l"(b))
#define ADD2(d, a, b) asm("add.rn.f32x2 %0, %1, %2;" : "=l"(d) : "l"(a), "l"(b))

// ---------------- device scratch ----------------
__device__ float g_W0T[96 * 256];
__device__ float g_W1PT[256 * 256];
__device__ float g_WIHT[256 * 2048];
__device__ float g_OW0ET[512 * 256];
__device__ float g_OW0MT[512 * 256];
__device__ float g_OW1T[256 * 256];
__device__ float g_OW2TP[256 * 192];
__device__ float g_ob2p[192];
__device__ float g_bsum[2048];
__device__ float g_ARX[2048 * 96];
__device__ float g_PRE0[2048 * 256];
__device__ float g_PRE[2048 * 256];
__device__ float g_GI[2048 * 2048];
__device__ float g_ZI[1024 * 256];
__device__ float g_H[2048 * 512];
__device__ float g_HP[2048 * 256];
__device__ float g_hping[2 * 4096];
__device__ float g_A2[262144 * 256];
__device__ float g_EM[2048 * 128];
__device__ float g_LS[2048 * 128];
__device__ float g_LM[2048 * 128];
__device__ int g_barc[257];

__device__ __forceinline__ float sigf(float x) { return 1.f / (1.f + __expf(-x)); }

// ---------------- prep ----------------
__global__ void k_prep(const float* __restrict__ w0, const float* __restrict__ w1p,
                       const float* __restrict__ wih, const float* __restrict__ ow0,
                       const float* __restrict__ ow1, const float* __restrict__ ow2,
                       const float* __restrict__ ob2, const float* __restrict__ bih,
                       const float* __restrict__ bhh, const float* __restrict__ mels) {
    int stride = gridDim.x * blockDim.x;
    int t0 = blockIdx.x * blockDim.x + threadIdx.x;
    for (int i = t0; i < 96 * 256; i += stride) {
        int k = i >> 8, p = i & 255;
        g_W0T[i] = (k < 80) ? w0[p * 80 + k] : 0.f;
    }
    for (int i = t0; i < 256 * 256; i += stride) {
        int k = i >> 8, p = i & 255;
        g_W1PT[i] = w1p[p * 256 + k];
    }
    for (int i = t0; i < 256 * 2048; i += stride) {
        int k = i >> 11, g = i & 2047;
        g_WIHT[i] = wih[g * 256 + k];
    }
    for (int i = t0; i < 512 * 256; i += stride) {
        int e = i >> 8, p = i & 255;
        g_OW0ET[i] = ow0[p * 1024 + e];
        g_OW0MT[i] = ow0[p * 1024 + 512 + e];
    }
    for (int i = t0; i < 256 * 256; i += stride) {
        int k = i >> 8, q = i & 255;
        g_OW1T[i] = ow1[q * 256 + k];
    }
    for (int i = t0; i < 256 * 192; i += stride) {
        int k = i / 192, r = i % 192;
        g_OW2TP[i] = (r < 161) ? ow2[r * 256 + k] : 0.f;
    }
    for (int i = t0; i < 192; i += stride) g_ob2p[i] = (i < 161) ? ob2[i] : 0.f;
    for (int i = t0; i < 2048; i += stride) g_bsum[i] = bih[i] + bhh[i];
    for (int i = t0; i < 2048 * 96; i += stride) {
        int row = i / 96, d = i % 96;
        int t = row >> 3, b = row & 7;
        g_ARX[i] = (d < 80 && t > 0) ? mels[(b * 80 + d) * 256 + (t - 1)] : 0.f;
    }
    for (int i = t0; i < 257; i += stride) g_barc[i] = 0;
}

// ---------------- generic tiled SGEMM, f32x2 packed ----------------
template <int ACT>
__global__ __launch_bounds__(256) void k_gemm(float* __restrict__ Cm,
                                              const float* __restrict__ Am,
                                              const float* __restrict__ BT,
                                              const float* __restrict__ bias,
                                              int R, int Ccols, int K) {
    __shared__ __align__(16) float As[32 * 68];
    __shared__ __align__(16) float Bs[32 * 128];
    int row0 = blockIdx.y * 64, col0 = blockIdx.x * 128;
    int tid = threadIdx.x;
    int tr = tid >> 4, tc = tid & 15;
    int r0 = tr * 4, c0 = tc * 8;
    ull acc0[8], acc1[8];
#pragma unroll
    for (int c = 0; c < 8; c++) { acc0[c] = 0ull; acc1[c] = 0ull; }
    for (int kt = 0; kt < K; kt += 32) {
        for (int i = tid; i < 2048; i += 256) {
            int r = i >> 5, k = i & 31;
            As[k * 68 + r] = Am[(row0 + r) * K + kt + k];
        }
        for (int i = tid; i < 4096; i += 256) {
            int k = i >> 7, c = i & 127;
            Bs[k * 128 + c] = BT[(kt + k) * Ccols + col0 + c];
        }
        __syncthreads();
#pragma unroll 8
        for (int k = 0; k < 32; k++) {
            ulonglong2 ap = *(const ulonglong2*)&As[k * 68 + r0];
            float4 b0 = *(const float4*)&Bs[k * 128 + c0];
            float4 b1 = *(const float4*)&Bs[k * 128 + c0 + 4];
            float wf[8] = {b0.x, b0.y, b0.z, b0.w, b1.x, b1.y, b1.z, b1.w};
#pragma unroll
            for (int c = 0; c < 8; c++) {
                ull wp;
                PACK2(wp, wf[c]);
                FMA2(acc0[c], ap.x, wp);
                FMA2(acc1[c], ap.y, wp);
            }
        }
        __syncthreads();
    }
#pragma unroll
    for (int c = 0; c < 8; c++) {
        int cc = col0 + c0 + c;
        float bb = bias ? bias[cc] : 0.f;
        float v0, v1, v2, v3;
        UNPK(v0, v1, acc0[c]);
        UNPK(v2, v3, acc1[c]);
        v0 += bb; v1 += bb; v2 += bb; v3 += bb;
        if (ACT) { v0 = fmaxf(v0, 0.f); v1 = fmaxf(v1, 0.f);
                   v2 = fmaxf(v2, 0.f); v3 = fmaxf(v3, 0.f); }
        Cm[(row0 + r0 + 0) * Ccols + cc] = v0;
        Cm[(row0 + r0 + 1) * Ccols + cc] = v1;
        Cm[(row0 + r0 + 2) * Ccols + cc] = v2;
        Cm[(row0 + r0 + 3) * Ccols + cc] = v3;
    }
}

// ---------------- LSTM grid barrier (single counter per step) ----------------
__device__ __forceinline__ void lbar(int slot) {
    __syncthreads();
    if (threadIdx.x == 0) {
        __threadfence();
        atomicAdd(&g_barc[slot], 1);
        while (*((volatile int*)&g_barc[slot]) < 64) __nanosleep(32);
        __threadfence();
    }
    __syncthreads();
}

// ---------------- persistent sequential LSTM ----------------
// 64 blocks x 256 threads. Block owns m in [bk*8, bk*8+8): 32 gate-rows.
// warp w: gate g=w&3, k-half=w>>2; lane l: k in {half*256+l+32j}.
// Thread register-blocks 8 rows x 4 batch-pairs (f32x2).
#define LSTM_SMEMF (16512 + 4096 + 512)

__global__ __launch_bounds__(256) void k_lstm(const float* __restrict__ whh) {
    extern __shared__ __align__(16) float sm[];
    float* Wsl = sm;                       // 32 x 516
    float* hs = sm + 16512;                // 4096 (h pairs, [k*8+b])
    ull* part = (ull*)(sm + 20608);        // 8 warps x 32 combos
    int tid = threadIdx.x;
    int m0 = blockIdx.x * 8;
    for (int i = tid; i < 32 * 512; i += 256) {
        int row = i >> 9, k = i & 511;
        int gate = row >> 3, ml = row & 7;
        Wsl[row * 516 + k] = whh[(gate * 512 + m0 + ml) * 512 + k];
    }
    if (tid < 64) __stcg(&g_hping[blockIdx.x * 64 + tid], 0.f);
    int w = tid >> 5, l = tid & 31;
    int g = w & 3, half = w >> 2;
    int k0 = half * 256 + l;
    int ml_u = tid >> 3, b_u = tid & 7;
    float c_reg = 0.f;
    lbar(0);
    for (int t = 0; t < Tt; t++) {
        int cur = t & 1, nxt = cur ^ 1;
        for (int i = tid; i < 2048; i += 256)
            ((float2*)hs)[i] = __ldcg(&((const float2*)g_hping)[cur * 2048 + i]);
        __syncthreads();
        ull acc[32];
#pragma unroll
        for (int i = 0; i < 32; i++) acc[i] = 0ull;
#pragma unroll
        for (int j = 0; j < 8; j++) {
            int k = k0 + 32 * j;
            ulonglong2 h01 = *(const ulonglong2*)&hs[k * 8];
            ulonglong2 h23 = *(const ulonglong2*)&hs[k * 8 + 4];
            ull hv0 = h01.x, hv1 = h01.y, hv2 = h23.x, hv3 = h23.y;
#pragma unroll
            for (int r = 0; r < 8; r++) {
                float wv = Wsl[(g * 8 + r) * 516 + k];
                ull wp;
                PACK2(wp, wv);
                FMA2(acc[r * 4 + 0], wp, hv0);
                FMA2(acc[r * 4 + 1], wp, hv1);
                FMA2(acc[r * 4 + 2], wp, hv2);
                FMA2(acc[r * 4 + 3], wp, hv3);
            }
        }
        // butterfly reduce: 32 accs over 32 lanes -> lane L holds combo L
#define REDST(OFF, CNT)                                                    \
        {                                                                  \
            bool hib = (l & OFF) != 0;                                     \
            _Pragma("unroll")                                              \
            for (int i = 0; i < CNT; i++) {                                \
                ull snd = hib ? acc[i] : acc[i + CNT];                     \
                ull rcv = __shfl_xor_sync(0xffffffffu, snd, OFF);          \
                ull kp = hib ? acc[i + CNT] : acc[i];                      \
                ADD2(acc[i], kp, rcv);                                     \
            }                                                              \
        }
        REDST(16, 16) REDST(8, 8) REDST(4, 4) REDST(2, 2) REDST(1, 1)
#undef REDST
        part[w * 32 + l] = acc[0];
        __syncthreads();
        if (tid < 64) {
            int p = b_u >> 1, hi = b_u & 1;
            int L = ml_u * 4 + p;
            float gv[4];
#pragma unroll
            for (int gate = 0; gate < 4; gate++) {
                ull s;
                ADD2(s, part[gate * 32 + L], part[(gate + 4) * 32 + L]);
                float lo, hif;
                UNPK(lo, hif, s);
                gv[gate] = hi ? hif : lo;
            }
            const float* gi = &g_GI[(t * 8 + b_u) * 2048 + m0 + ml_u];
            float ig = gv[0] + gi[0];
            float fg = gv[1] + gi[512];
            float gg = gv[2] + gi[1024];
            float og = gv[3] + gi[1536];
            float cn = sigf(fg) * c_reg + sigf(ig) * tanhf(gg);
            float h = sigf(og) * tanhf(cn);
            c_reg = cn;
            __stcg(&g_hping[nxt * 4096 + (m0 + ml_u) * 8 + b_u], h);
            g_H[(t * 8 + b_u) * 512 + m0 + ml_u] = h;
        }
        lbar(t + 1);
    }
}

// ---------------- GEMM2: A2 = relu(A1 @ OW1T + ob1), f32x2 packed ----------------
__global__ __launch_bounds__(256, 2) void k_g2(const float* __restrict__ ob1) {
    __shared__ __align__(16) float As[32 * 136];
    __shared__ __align__(16) float Bs[32 * 128];
    int tb = blockIdx.y;
    int b = tb & 7;
    int col0 = blockIdx.x * 128;
    int tid = threadIdx.x;
    int tr = tid >> 4, tc = tid & 15;
    int r0 = tr * 8, c0 = tc * 8;
    ull acc[4][8];
#pragma unroll
    for (int p = 0; p < 4; p++)
#pragma unroll
        for (int c = 0; c < 8; c++) acc[p][c] = 0ull;
    for (int kt = 0; kt < 256; kt += 32) {
        for (int i = tid; i < 4096; i += 256) {
            int k = i & 31, r = i >> 5;
            float z = g_ZI[((b << 7) + r) * 256 + kt + k] + g_HP[tb * 256 + kt + k];
            As[k * 136 + r] = fmaxf(z, 0.f);
        }
        for (int i = tid; i < 4096; i += 256) {
            int c = i & 127, k = i >> 7;
            Bs[k * 128 + c] = g_OW1T[(kt + k) * 256 + col0 + c];
        }
        __syncthreads();
#pragma unroll 8
        for (int k = 0; k < 32; k++) {
            ulonglong2 aA = *(const ulonglong2*)&As[k * 136 + r0];
            ulonglong2 aB = *(const ulonglong2*)&As[k * 136 + r0 + 4];
            float4 w0 = *(const float4*)&Bs[k * 128 + c0];
            float4 w1 = *(const float4*)&Bs[k * 128 + c0 + 4];
            float wf[8] = {w0.x, w0.y, w0.z, w0.w, w1.x, w1.y, w1.z, w1.w};
#pragma unroll
            for (int c = 0; c < 8; c++) {
                ull wp;
                PACK2(wp, wf[c]);
                FMA2(acc[0][c], aA.x, wp);
                FMA2(acc[1][c], aA.y, wp);
                FMA2(acc[2][c], aB.x, wp);
                FMA2(acc[3][c], aB.y, wp);
            }
        }
        __syncthreads();
    }
    int rowb = tb * 128 + r0;
#pragma unroll
    for (int p = 0; p < 4; p++) {
        float lo[8], hi[8];
#pragma unroll
        for (int c = 0; c < 8; c++) {
            UNPK(lo[c], hi[c], acc[p][c]);
            float bb = ob1[col0 + c0 + c];
            lo[c] = fmaxf(lo[c] + bb, 0.f);
            hi[c] = fmaxf(hi[c] + bb, 0.f);
        }
        float* d0 = &g_A2[(rowb + 2 * p) * 256 + col0 + c0];
        float* d1 = &g_A2[(rowb + 2 * p + 1) * 256 + col0 + c0];
        *(float4*)d0 = make_float4(lo[0], lo[1], lo[2], lo[3]);
        *(float4*)(d0 + 4) = make_float4(lo[4], lo[5], lo[6], lo[7]);
        *(float4*)d1 = make_float4(hi[0], hi[1], hi[2], hi[3]);
        *(float4*)(d1 + 4) = make_float4(hi[4], hi[5], hi[6], hi[7]);
    }
}

// ---------------- GEMM3 + emission fused, f32x2 packed ----------------
#define G3_AS 0
#define G3_WS 2304
#define G3_PM 8448
#define G3_XT 20736
#define G3_SMEMF 20832

__global__ __launch_bounds__(256, 2) void k_g3em(const float* __restrict__ mels,
                                                 const int* __restrict__ inputs_len) {
    extern __shared__ __align__(16) float sm3[];
    float* As = sm3 + G3_AS;
    float* Ws = sm3 + G3_WS;
    float* Pm = sm3 + G3_PM;
    float* xt = sm3 + G3_XT;
    int bid = blockIdx.x;
    int tb = bid >> 1, half = bid & 1;
    int t = tb >> 3, b = tb & 7;
    int rowbase = tb * 128 + half * 64;
    int tid = threadIdx.x;
    if (tid < 80) xt[tid] = mels[(b * 80 + tid) * 256 + t];
    int tr = tid >> 4, tc = tid & 15;
    int r0 = tr * 4, c0 = tc * 12;
    ull acc[4][6];
#pragma unroll
    for (int ri = 0; ri < 4; ri++)
#pragma unroll
        for (int cj = 0; cj < 6; cj++) acc[ri][cj] = 0ull;
    for (int kt = 0; kt < 256; kt += 32) {
        for (int i = tid; i < 2048; i += 256) {
            int k = i & 31, r = i >> 5;
            As[k * 72 + r] = g_A2[(rowbase + r) * 256 + kt + k];
        }
        for (int i = tid; i < 1536; i += 256)
            ((float4*)Ws)[i] = ((const float4*)(g_OW2TP + kt * 192))[i];
        __syncthreads();
#pragma unroll 8
        for (int k = 0; k < 32; k++) {
            float4 av = *(const float4*)&As[k * 72 + r0];
            ull ap[4];
            PACK2(ap[0], av.x);
            PACK2(ap[1], av.y);
            PACK2(ap[2], av.z);
            PACK2(ap[3], av.w);
            ulonglong2 wA = *(const ulonglong2*)&Ws[k * 192 + c0];
            ulonglong2 wB = *(const ulonglong2*)&Ws[k * 192 + c0 + 4];
            ulonglong2 wC = *(const ulonglong2*)&Ws[k * 192 + c0 + 8];
            ull wv[6] = {wA.x, wA.y, wB.x, wB.y, wC.x, wC.y};
#pragma unroll
            for (int cj = 0; cj < 6; cj++) {
                FMA2(acc[0][cj], ap[0], wv[cj]);
                FMA2(acc[1][cj], ap[1], wv[cj]);
                FMA2(acc[2][cj], ap[2], wv[cj]);
                FMA2(acc[3][cj], ap[3], wv[cj]);
            }
        }
        __syncthreads();
    }
#pragma unroll
    for (int ri = 0; ri < 4; ri++)
#pragma unroll
        for (int cj = 0; cj < 6; cj++) {
            float lo, hi;
            UNPK(lo, hi, acc[ri][cj]);
            int col = c0 + 2 * cj;
            Pm[(r0 + ri) * 192 + col] = lo + g_ob2p[col];
            Pm[(r0 + ri) * 192 + col + 1] = hi + g_ob2p[col + 1];
        }
    __syncthreads();
    {
        int row = tid >> 2, q = tid & 3;
        int ilen = inputs_len[b];
        float accv = 0.f;
        for (int d = q * 20; d < q * 20 + 20; d++) {
            float mean = Pm[row * 192 + d];
            float sh = Pm[row * 192 + 80 + d];
            float sp = (sh > 15.f) ? sh : __logf(1.f + __expf(sh));
            float stdv = sp + 0.001f;
            float z = (xt[d] - mean) / stdv;
            accv += -0.5f * z * z - __logf(stdv);
        }
        accv += __shfl_down_sync(0xffffffffu, accv, 2, 4);
        accv += __shfl_down_sync(0xffffffffu, accv, 1, 4);
        if (q == 0) {
            int n = half * 64 + row;
            float em = accv - 40.f * LOG2PI;
            g_EM[tb * 128 + n] = (n < ilen) ? em : 0.f;
            float tv = Pm[row * 192 + 160];
            float s_move = 1.f / (1.f + __expf(-tv));
            float s_stay = 1.f - s_move;
            g_LS[tb * 128 + n] = __logf(fmaxf(s_stay, EPSC));
            g_LM[tb * 128 + n] = __logf(fmaxf(s_move, EPSC));
        }
    }
}

// ---------------- alpha recursion: one block, 8 independent warps ----------------
__global__ __launch_bounds__(256) void k_alpha(float* __restrict__ out,
                                               const int* __restrict__ inputs_len,
                                               const int* __restrict__ mel_lens) {
    int tid = threadIdx.x;
    int b = tid >> 5, l = tid & 31;
    int ilen = inputs_len[b], mlen = mel_lens[b];
    float la[4];
    float lp = 0.f;
    bool mk[4];
#pragma unroll
    for (int j = 0; j < 4; j++) mk[j] = (l * 4 + j) < ilen;
    for (int t = 0; t < Tt; t++) {
        int base = ((t << 3) + b) * 128 + l * 4;
        float4 em4 = *(const float4*)&g_EM[base];
        float em[4] = {em4.x, em4.y, em4.z, em4.w};
        float v[4];
        if (t == 0) {
#pragma unroll
            for (int j = 0; j < 4; j++)
                v[j] = ((l == 0 && j == 0) ? 0.f : NEGV) + em[j];
        } else {
            float4 ls4 = *(const float4*)&g_LS[base];
            float4 lm4 = *(const float4*)&g_LM[base];
            float lau = __shfl_up_sync(0xffffffffu, la[3], 1);
            float lmu = __shfl_up_sync(0xffffffffu, lm4.w, 1);
            float lam1[4] = {lau, la[0], la[1], la[2]};
            float lmm1[4] = {lmu, lm4.x, lm4.y, lm4.z};
            float ls[4] = {ls4.x, ls4.y, ls4.z, ls4.w};
#pragma unroll
            for (int j = 0; j < 4; j++) {
                float stay = la[j] + ls[j];
                float leave = (l == 0 && j == 0) ? NEGV : lam1[j] + lmm1[j];
                float mx = fmaxf(stay, leave), mn = fminf(stay, leave);
                float ladd = mx + __logf(1.f + __expf(mn - mx));
                v[j] = em[j] + (mk[j] ? ladd : NEGV);
            }
        }
        float m = fmaxf(fmaxf(v[0], v[1]), fmaxf(v[2], v[3]));
#pragma unroll
        for (int off = 16; off; off >>= 1)
            m = fmaxf(m, __shfl_xor_sync(0xffffffffu, m, off));
        float s = __expf(v[0] - m) + __expf(v[1] - m) +
                  __expf(v[2] - m) + __expf(v[3] - m);
#pragma unroll
        for (int off = 16; off; off >>= 1)
            s += __shfl_xor_sync(0xffffffffu, s, off);
        float logc = m + __logf(s);
#pragma unroll
        for (int j = 0; j < 4; j++) la[j] = v[j] - logc;
        *(float4*)&out[8 + ((b << 8) + t) * 128 + l * 4] =
            make_float4(la[0], la[1], la[2], la[3]);
        if (l == 0 && t < mlen) lp += logc;
    }
    if (l == 0) out[b] = lp;
}

// ---------------- launch ----------------
extern "C" void kernel_launch(void* const* d_in, const int* in_sizes, int n_in,
                              void* d_out, int out_size) {
    const float* inputs = (const float*)d_in[0];
    const float* mels = (const float*)d_in[1];
    const float* w0 = (const float*)d_in[2];
    const float* w1p = (const float*)d_in[3];
    const float* wih = (const float*)d_in[4];
    const float* whh = (const float*)d_in[5];
    const float* bih = (const float*)d_in[6];
    const float* bhh = (const float*)d_in[7];
    const float* ow0 = (const float*)d_in[8];
    const float* ob0 = (const float*)d_in[9];
    const float* ow1 = (const float*)d_in[10];
    const float* ob1 = (const float*)d_in[11];
    const float* ow2 = (const float*)d_in[12];
    const float* ob2 = (const float*)d_in[13];
    const int* inputs_len = (const int*)d_in[14];
    const int* mel_lens = (const int*)d_in[15];
    float* out = (float*)d_out;

    cudaFuncSetAttribute(k_lstm, cudaFuncAttributeMaxDynamicSharedMemorySize,
                         LSTM_SMEMF * 4);
    cudaFuncSetAttribute(k_g3em, cudaFuncAttributeMaxDynamicSharedMemorySize,
                         G3_SMEMF * 4);

    float* pre0;  cudaGetSymbolAddress((void**)&pre0, g_PRE0);
    float* pre;   cudaGetSymbolAddress((void**)&pre, g_PRE);
    float* gi;    cudaGetSymbolAddress((void**)&gi, g_GI);
    float* zi;    cudaGetSymbolAddress((void**)&zi, g_ZI);
    float* hh;    cudaGetSymbolAddress((void**)&hh, g_H);
    float* hpm;   cudaGetSymbolAddress((void**)&hpm, g_HP);
    float* arx;   cudaGetSymbolAddress((void**)&arx, g_ARX);
    float* w0t;   cudaGetSymbolAddress((void**)&w0t, g_W0T);
    float* w1pt;  cudaGetSymbolAddress((void**)&w1pt, g_W1PT);
    float* wiht;  cudaGetSymbolAddress((void**)&wiht, g_WIHT);
    float* ow0et; cudaGetSymbolAddress((void**)&ow0et, g_OW0ET);
    float* ow0mt; cudaGetSymbolAddress((void**)&ow0mt, g_OW0MT);
    float* bsum;  cudaGetSymbolAddress((void**)&bsum, g_bsum);

    k_prep<<<256, 256>>>(w0, w1p, wih, ow0, ow1, ow2, ob2, bih, bhh, mels);
    k_gemm<1><<<dim3(2, 32), 256>>>(pre0, arx, w0t, nullptr, 2048, 256, 96);
    k_gemm<1><<<dim3(2, 32), 256>>>(pre, pre0, w1pt, nullptr, 2048, 256, 256);
    k_gemm<0><<<dim3(16, 32), 256>>>(gi, pre, wiht, bsum, 2048, 2048, 256);
    k_gemm<0><<<dim3(2, 16), 256>>>(zi, inputs, ow0et, nullptr, 1024, 256, 512);
    k_lstm<<<64, 256, LSTM_SMEMF * 4>>>(whh);
    k_gemm<0><<<dim3(2, 32), 256>>>(hpm, hh, ow0mt, ob0, 2048, 256, 512);
    k_g2<<<dim3(2, 2048), 256>>>(ob1);
    k_g3em<<<4096, 256, G3_SMEMF * 4>>>(mels, inputs_len);
    k_alpha<<<1, 256>>>(out, inputs_len, mel_lens);
    (void)in_sizes; (void)n_in; (void)out_size;
}

// round 9
// speedup vs baseline: 1.8248x; 1.1232x over previous
#include <cuda_runtime.h>
#include <cstdint>
#include <math.h>

#define Tt 256
#define NEGV -1e10f
#define EPSC 1e-4f
#define LOG2PI 1.8378770664093453f

typedef unsigned long long ull;
typedef unsigned int u32;

#define PACK2(out, x) asm("mov.b64 %0, {%1, %1};" : "=l"(out) : "r"(__float_as_uint(x)))
#define UNPK(lo, hi, in) { unsigned int ulo, uhi; \
    asm("mov.b64 {%0, %1}, %2;" : "=r"(ulo), "=r"(uhi) : "l"(in)); \
    lo = __uint_as_float(ulo); hi = __uint_as_float(uhi); }
#define FMA2(d, a, b) asm("fma.rn.f32x2 %0, %1, %2, %0;" : "+l"(d) : "l"(a), "l"(b))
#define ADD2(d, a, b) asm("add.rn.f32x2 %0, %1, %2;" : "=l"(d) : "l"(a), "l"(b))

// ---- bf16 bit helpers ----
__device__ __forceinline__ u32 bf16_bits(float a) {
    u32 u = __float_as_uint(a);
    return (u + 0x7FFFu + ((u >> 16) & 1u)) >> 16;
}
__device__ __forceinline__ void bfsplit2(float a0, float a1, u32& hi, u32& lo) {
    u32 h0 = bf16_bits(a0);
    u32 h1 = bf16_bits(a1);
    float h0f = __uint_as_float(h0 << 16);
    float h1f = __uint_as_float(h1 << 16);
    u32 l0 = bf16_bits(a0 - h0f);
    u32 l1 = bf16_bits(a1 - h1f);
    hi = (h1 << 16) | h0;
    lo = (l1 << 16) | l0;
}

__device__ __forceinline__ u32 smem_to_u32(const void* p) {
    u32 a;
    asm("{ .reg .u64 t; cvta.to.shared.u64 t, %1; cvt.u32.u64 %0, t; }"
        : "=r"(a) : "l"(p));
    return a;
}
__device__ __forceinline__ void ldmx4(u32& r0, u32& r1, u32& r2, u32& r3, u32 addr) {
    asm volatile("ldmatrix.sync.aligned.m8n8.x4.shared.b16 {%0,%1,%2,%3}, [%4];"
                 : "=r"(r0), "=r"(r1), "=r"(r2), "=r"(r3) : "r"(addr));
}
__device__ __forceinline__ void mma_bf16(float* c, const u32* a, const u32* b) {
    asm volatile("mma.sync.aligned.m16n8k16.row.col.f32.bf16.bf16.f32 "
                 "{%0,%1,%2,%3}, {%4,%5,%6,%7}, {%8,%9}, {%0,%1,%2,%3};"
                 : "+f"(c[0]), "+f"(c[1]), "+f"(c[2]), "+f"(c[3])
                 : "r"(a[0]), "r"(a[1]), "r"(a[2]), "r"(a[3]),
                   "r"(b[0]), "r"(b[1]));
}

// ---------------- device scratch ----------------
__device__ float g_W0T[96 * 256];
__device__ float g_W1PT[256 * 256];
__device__ float g_WIHT[256 * 2048];
__device__ float g_OW0ET[512 * 256];
__device__ float g_OW0MT[512 * 256];
__device__ float g_bsum[2048];
__device__ float g_ARX[2048 * 96];
__device__ float g_PRE0[2048 * 256];
__device__ float g_PRE[2048 * 256];
__device__ float g_GI[2048 * 2048];
__device__ float g_ZI[1024 * 256];
__device__ float g_H[2048 * 512];
__device__ float g_HP[2048 * 256];
__device__ float g_hping[2 * 4096];
__device__ float g_EMa[2048 * 128];
__device__ float g_EMb[2048 * 128];
__device__ float g_LS[2048 * 128];
__device__ float g_LM[2048 * 128];
__device__ float g_ob2perm[192];
__device__ unsigned short g_B1h[256 * 256];   // ow1 bf16 hi, row-major [n][k]
__device__ unsigned short g_B1l[256 * 256];
__device__ unsigned short g_B2h[192 * 256];   // ow2 permuted bf16 hi, [n][k]
__device__ unsigned short g_B2l[192 * 256];
__device__ u32 g_A2h[(size_t)2048 * 128 * 128];  // A2 bf16-hi pairs [tb][r][k/2]
__device__ u32 g_A2l[(size_t)2048 * 128 * 128];
__device__ int g_barc[257];

__device__ __forceinline__ float sigf(float x) { return 1.f / (1.f + __expf(-x)); }

// ---------------- prep ----------------
__global__ void k_prep(const float* __restrict__ w0, const float* __restrict__ w1p,
                       const float* __restrict__ wih, const float* __restrict__ ow0,
                       const float* __restrict__ ow1, const float* __restrict__ ow2,
                       const float* __restrict__ ob2, const float* __restrict__ bih,
                       const float* __restrict__ bhh, const float* __restrict__ mels) {
    int stride = gridDim.x * blockDim.x;
    int t0 = blockIdx.x * blockDim.x + threadIdx.x;
    for (int i = t0; i < 96 * 256; i += stride) {
        int k = i >> 8, p = i & 255;
        g_W0T[i] = (k < 80) ? w0[p * 80 + k] : 0.f;
    }
    for (int i = t0; i < 256 * 256; i += stride) {
        int k = i >> 8, p = i & 255;
        g_W1PT[i] = w1p[p * 256 + k];
    }
    for (int i = t0; i < 256 * 2048; i += stride) {
        int k = i >> 11, g = i & 2047;
        g_WIHT[i] = wih[g * 256 + k];
    }
    for (int i = t0; i < 512 * 256; i += stride) {
        int e = i >> 8, p = i & 255;
        g_OW0ET[i] = ow0[p * 1024 + e];
        g_OW0MT[i] = ow0[p * 1024 + 512 + e];
    }
    for (int i = t0; i < 2048; i += stride) g_bsum[i] = bih[i] + bhh[i];
    for (int i = t0; i < 2048 * 96; i += stride) {
        int row = i / 96, d = i % 96;
        int t = row >> 3, b = row & 7;
        g_ARX[i] = (d < 80 && t > 0) ? mels[(b * 80 + d) * 256 + (t - 1)] : 0.f;
    }
    for (int i = t0; i < 257; i += stride) g_barc[i] = 0;
    // B1 = ow1 bf16 hi/lo (row-major [n][k])
    for (int i = t0; i < 65536; i += stride) {
        float w = ow1[i];
        u32 hb = bf16_bits(w);
        float hf = __uint_as_float(hb << 16);
        u32 lb = bf16_bits(w - hf);
        g_B1h[i] = (unsigned short)hb;
        g_B1l[i] = (unsigned short)lb;
    }
    // B2 = ow2 rows permuted (mean/std interleaved, tv@160, zero pad to 192)
    for (int i = t0; i < 192 * 256; i += stride) {
        int n = i >> 8, k = i & 255;
        float w = 0.f;
        if (n < 160) {
            int sf = (n & 1) ? (80 + (n >> 1)) : (n >> 1);
            w = ow2[sf * 256 + k];
        } else if (n == 160) {
            w = ow2[160 * 256 + k];
        }
        u32 hb = bf16_bits(w);
        float hf = __uint_as_float(hb << 16);
        u32 lb = bf16_bits(w - hf);
        g_B2h[i] = (unsigned short)hb;
        g_B2l[i] = (unsigned short)lb;
    }
    for (int i = t0; i < 192; i += stride) {
        float v = 0.f;
        if (i < 160) v = ob2[(i & 1) ? (80 + (i >> 1)) : (i >> 1)];
        else if (i == 160) v = ob2[160];
        g_ob2perm[i] = v;
    }
}

// ---------------- generic tiled SGEMM, f32x2 packed ----------------
template <int ACT>
__global__ __launch_bounds__(256) void k_gemm(float* __restrict__ Cm,
                                              const float* __restrict__ Am,
                                              const float* __restrict__ BT,
                                              const float* __restrict__ bias,
                                              int R, int Ccols, int K) {
    __shared__ __align__(16) float As[32 * 68];
    __shared__ __align__(16) float Bs[32 * 128];
    int row0 = blockIdx.y * 64, col0 = blockIdx.x * 128;
    int tid = threadIdx.x;
    int tr = tid >> 4, tc = tid & 15;
    int r0 = tr * 4, c0 = tc * 8;
    ull acc0[8], acc1[8];
#pragma unroll
    for (int c = 0; c < 8; c++) { acc0[c] = 0ull; acc1[c] = 0ull; }
    for (int kt = 0; kt < K; kt += 32) {
        for (int i = tid; i < 2048; i += 256) {
            int r = i >> 5, k = i & 31;
            As[k * 68 + r] = Am[(row0 + r) * K + kt + k];
        }
        for (int i = tid; i < 4096; i += 256) {
            int k = i >> 7, c = i & 127;
            Bs[k * 128 + c] = BT[(kt + k) * Ccols + col0 + c];
        }
        __syncthreads();
#pragma unroll 8
        for (int k = 0; k < 32; k++) {
            ulonglong2 ap = *(const ulonglong2*)&As[k * 68 + r0];
            float4 b0 = *(const float4*)&Bs[k * 128 + c0];
            float4 b1 = *(const float4*)&Bs[k * 128 + c0 + 4];
            float wf[8] = {b0.x, b0.y, b0.z, b0.w, b1.x, b1.y, b1.z, b1.w};
#pragma unroll
            for (int c = 0; c < 8; c++) {
                ull wp;
                PACK2(wp, wf[c]);
                FMA2(acc0[c], ap.x, wp);
                FMA2(acc1[c], ap.y, wp);
            }
        }
        __syncthreads();
    }
#pragma unroll
    for (int c = 0; c < 8; c++) {
        int cc = col0 + c0 + c;
        float bb = bias ? bias[cc] : 0.f;
        float v0, v1, v2, v3;
        UNPK(v0, v1, acc0[c]);
        UNPK(v2, v3, acc1[c]);
        v0 += bb; v1 += bb; v2 += bb; v3 += bb;
        if (ACT) { v0 = fmaxf(v0, 0.f); v1 = fmaxf(v1, 0.f);
                   v2 = fmaxf(v2, 0.f); v3 = fmaxf(v3, 0.f); }
        Cm[(row0 + r0 + 0) * Ccols + cc] = v0;
        Cm[(row0 + r0 + 1) * Ccols + cc] = v1;
        Cm[(row0 + r0 + 2) * Ccols + cc] = v2;
        Cm[(row0 + r0 + 3) * Ccols + cc] = v3;
    }
}

// ---------------- LSTM (R5, unchanged) ----------------
__device__ __forceinline__ void lbar(int slot) {
    __syncthreads();
    if (threadIdx.x == 0) {
        __threadfence();
        atomicAdd(&g_barc[slot], 1);
        while (*((volatile int*)&g_barc[slot]) < 64) __nanosleep(32);
        __threadfence();
    }
    __syncthreads();
}

#define LSTM_SMEMF (16512 + 4096 + 512)
__global__ __launch_bounds__(256) void k_lstm(const float* __restrict__ whh) {
    extern __shared__ __align__(16) float sm[];
    float* Wsl = sm;
    float* hs = sm + 16512;
    ull* part = (ull*)(sm + 20608);
    int tid = threadIdx.x;
    int m0 = blockIdx.x * 8;
    for (int i = tid; i < 32 * 512; i += 256) {
        int row = i >> 9, k = i & 511;
        int gate = row >> 3, ml = row & 7;
        Wsl[row * 516 + k] = whh[(gate * 512 + m0 + ml) * 512 + k];
    }
    if (tid < 64) __stcg(&g_hping[blockIdx.x * 64 + tid], 0.f);
    int w = tid >> 5, l = tid & 31;
    int g = w & 3;
    int khf = w >> 2;
    int k0 = khf * 256 + l;
    int ml_u = tid >> 3, b_u = tid & 7;
    float c_reg = 0.f;
    lbar(0);
    for (int t = 0; t < Tt; t++) {
        int cur = t & 1, nxt = cur ^ 1;
        for (int i = tid; i < 2048; i += 256)
            ((float2*)hs)[i] = __ldcg(&((const float2*)g_hping)[cur * 2048 + i]);
        __syncthreads();
        ull acc[32];
#pragma unroll
        for (int i = 0; i < 32; i++) acc[i] = 0ull;
#pragma unroll
        for (int j = 0; j < 8; j++) {
            int k = k0 + 32 * j;
            ulonglong2 h01 = *(const ulonglong2*)&hs[k * 8];
            ulonglong2 h23 = *(const ulonglong2*)&hs[k * 8 + 4];
            ull hv0 = h01.x, hv1 = h01.y, hv2 = h23.x, hv3 = h23.y;
#pragma unroll
            for (int r = 0; r < 8; r++) {
                float wv = Wsl[(g * 8 + r) * 516 + k];
                ull wp;
                PACK2(wp, wv);
                FMA2(acc[r * 4 + 0], wp, hv0);
                FMA2(acc[r * 4 + 1], wp, hv1);
                FMA2(acc[r * 4 + 2], wp, hv2);
                FMA2(acc[r * 4 + 3], wp, hv3);
            }
        }
#define REDST(OFF, CNT)                                                    \
        {                                                                  \
            bool hib = (l & OFF) != 0;                                     \
            _Pragma("unroll")                                              \
            for (int i = 0; i < CNT; i++) {                                \
                ull snd = hib ? acc[i] : acc[i + CNT];                     \
                ull rcv = __shfl_xor_sync(0xffffffffu, snd, OFF);          \
                ull kp = hib ? acc[i + CNT] : acc[i];                      \
                ADD2(acc[i], kp, rcv);                                     \
            }                                                              \
        }
        REDST(16, 16) REDST(8, 8) REDST(4, 4) REDST(2, 2) REDST(1, 1)
#undef REDST
        part[w * 32 + l] = acc[0];
        __syncthreads();
        if (tid < 64) {
            int p = b_u >> 1, hi = b_u & 1;
            int L = ml_u * 4 + p;
            float gv[4];
#pragma unroll
            for (int gate = 0; gate < 4; gate++) {
                ull s;
                ADD2(s, part[gate * 32 + L], part[(gate + 4) * 32 + L]);
                float lo, hif;
                UNPK(lo, hif, s);
                gv[gate] = hi ? hif : lo;
            }
            const float* gi = &g_GI[(t * 8 + b_u) * 2048 + m0 + ml_u];
            float ig = gv[0] + gi[0];
            float fg = gv[1] + gi[512];
            float gg = gv[2] + gi[1024];
            float og = gv[3] + gi[1536];
            float cn = sigf(fg) * c_reg + sigf(ig) * tanhf(gg);
            float h = sigf(og) * tanhf(cn);
            c_reg = cn;
            __stcg(&g_hping[nxt * 4096 + (m0 + ml_u) * 8 + b_u], h);
            g_H[(t * 8 + b_u) * 512 + m0 + ml_u] = h;
        }
        lbar(t + 1);
    }
}

// ---------------- GEMM2 via HMMA: A2 = relu(A1 @ ow1^T + ob1) ----------------
// grid (2, 2048): x = n-half (128 cols), y = tb. 256 threads (8 warps).
// smem u16 tiles stride 72. Ah 0, Al 18432, Bh 36864, Bl 55296. Total 73728 B.
#define G2_SMEMB 73728

__global__ __launch_bounds__(256, 1) void k_g2mma(const float* __restrict__ ob1) {
    extern __shared__ __align__(16) char smc2[];
    u32 sbase = smem_to_u32(smc2);
    u32* Ah32 = (u32*)smc2;
    u32* Al32 = (u32*)(smc2 + 18432);
    u32* Bh32 = (u32*)(smc2 + 36864);
    u32* Bl32 = (u32*)(smc2 + 55296);
    int tb = blockIdx.y;
    int col0 = blockIdx.x * 128;
    int b = tb & 7;
    int tid = threadIdx.x;
    int warp = tid >> 5, lane = tid & 31;
    int wr = (warp & 3) * 32;
    int wc = (warp >> 2) * 64;
    float acc[2][8][4];
#pragma unroll
    for (int mt = 0; mt < 2; mt++)
#pragma unroll
        for (int nt = 0; nt < 8; nt++)
#pragma unroll
            for (int q = 0; q < 4; q++) acc[mt][nt][q] = 0.f;

    const u32* gB1h = (const u32*)g_B1h;
    const u32* gB1l = (const u32*)g_B1l;
    u32 lmrow = (u32)(lane & 15);
    u32 lmk = (u32)((lane >> 4) << 3);

    for (int kc = 0; kc < 4; kc++) {
        int k0 = kc * 64;
        // stage A1 chunk (compute + split)
        for (int i = tid; i < 4096; i += 256) {
            int r = i >> 5, kp = i & 31;
            float2 za = *(const float2*)&g_ZI[(size_t)(b * 128 + r) * 256 + k0 + 2 * kp];
            float2 hp = *(const float2*)&g_HP[(size_t)tb * 256 + k0 + 2 * kp];
            float a0 = fmaxf(za.x + hp.x, 0.f);
            float a1 = fmaxf(za.y + hp.y, 0.f);
            u32 hi, lo;
            bfsplit2(a0, a1, hi, lo);
            Ah32[r * 36 + kp] = hi;
            Al32[r * 36 + kp] = lo;
        }
        // stage B chunk
        for (int i = tid; i < 4096; i += 256) {
            int n = i >> 5, kp = i & 31;
            size_t gsrc = (size_t)(col0 + n) * 128 + (k0 >> 1) + kp;
            Bh32[n * 36 + kp] = gB1h[gsrc];
            Bl32[n * 36 + kp] = gB1l[gsrc];
        }
        __syncthreads();
#pragma unroll
        for (int ks = 0; ks < 4; ks++) {
            u32 kk = (u32)(ks * 16);
            u32 a_h[2][4], a_l[2][4];
#pragma unroll
            for (int mt = 0; mt < 2; mt++) {
                u32 ad = sbase + (((u32)(wr + mt * 16) + lmrow) * 72 + kk + lmk) * 2;
                ldmx4(a_h[mt][0], a_h[mt][1], a_h[mt][2], a_h[mt][3], ad);
                ldmx4(a_l[mt][0], a_l[mt][1], a_l[mt][2], a_l[mt][3], ad + 18432);
            }
            u32 b_h[8][2], b_l[8][2];
#pragma unroll
            for (int np = 0; np < 4; np++) {
                u32 bd = sbase + 36864 +
                         (((u32)(wc + np * 16) + lmrow) * 72 + kk + lmk) * 2;
                u32 r0, r1, r2, r3;
                ldmx4(r0, r1, r2, r3, bd);
                b_h[np * 2][0] = r0; b_h[np * 2][1] = r2;
                b_h[np * 2 + 1][0] = r1; b_h[np * 2 + 1][1] = r3;
                ldmx4(r0, r1, r2, r3, bd + 18432);
                b_l[np * 2][0] = r0; b_l[np * 2][1] = r2;
                b_l[np * 2 + 1][0] = r1; b_l[np * 2 + 1][1] = r3;
            }
#pragma unroll
            for (int mt = 0; mt < 2; mt++)
#pragma unroll
                for (int nt = 0; nt < 8; nt++) {
                    mma_bf16(acc[mt][nt], a_h[mt], b_h[nt]);
                    mma_bf16(acc[mt][nt], a_l[mt], b_h[nt]);
                    mma_bf16(acc[mt][nt], a_h[mt], b_l[nt]);
                }
        }
        __syncthreads();
    }
    // epilogue: +ob1, relu, split, store A2 bf16 pairs
#pragma unroll
    for (int mt = 0; mt < 2; mt++) {
        int r = wr + mt * 16 + (lane >> 2);
#pragma unroll
        for (int nt = 0; nt < 8; nt++) {
            int col = wc + nt * 8 + (lane & 3) * 2;
            int gc = col0 + col;
            float bb0 = ob1[gc], bb1 = ob1[gc + 1];
            float v0 = fmaxf(acc[mt][nt][0] + bb0, 0.f);
            float v1 = fmaxf(acc[mt][nt][1] + bb1, 0.f);
            u32 hp, lp;
            bfsplit2(v0, v1, hp, lp);
            size_t dst = ((size_t)tb * 128 + r) * 128 + (gc >> 1);
            g_A2h[dst] = hp;
            g_A2l[dst] = lp;
            v0 = fmaxf(acc[mt][nt][2] + bb0, 0.f);
            v1 = fmaxf(acc[mt][nt][3] + bb1, 0.f);
            bfsplit2(v0, v1, hp, lp);
            dst = ((size_t)tb * 128 + r + 8) * 128 + (gc >> 1);
            g_A2h[dst] = hp;
            g_A2l[dst] = lp;
        }
    }
}

// ---------------- GEMM3 via HMMA + emission epilogue ----------------
// grid (2, 2048): x = n-half (96 perm cols), y = tb. 256 threads.
// smem: Ah 0 (18432), Al 18432, Bh 36864 (13824), Bl 50688, Ps 64512 (51200), xt 115712.
#define G3_SMEMB 116096

__global__ __launch_bounds__(256, 1) void k_g3mma(const float* __restrict__ mels,
                                                  const int* __restrict__ inputs_len) {
    extern __shared__ __align__(16) char smc3[];
    u32 sbase = smem_to_u32(smc3);
    u32* Ah32 = (u32*)smc3;
    u32* Al32 = (u32*)(smc3 + 18432);
    u32* Bh32 = (u32*)(smc3 + 36864);
    u32* Bl32 = (u32*)(smc3 + 50688);
    float* Ps = (float*)(smc3 + 64512);
    float* xt = (float*)(smc3 + 115712);
    int tb = blockIdx.y;
    int nh = blockIdx.x;
    int col0 = nh * 96;
    int t = tb >> 3, b = tb & 7;
    int tid = threadIdx.x;
    int warp = tid >> 5, lane = tid & 31;
    int wr = (warp & 3) * 32;
    int wc = (warp >> 2) * 48;
    if (tid < 80) xt[tid] = mels[(b * 80 + tid) * 256 + t];
    float acc[2][6][4];
#pragma unroll
    for (int mt = 0; mt < 2; mt++)
#pragma unroll
        for (int nt = 0; nt < 6; nt++)
#pragma unroll
            for (int q = 0; q < 4; q++) acc[mt][nt][q] = 0.f;

    const u32* gB2h = (const u32*)g_B2h;
    const u32* gB2l = (const u32*)g_B2l;
    u32 lmrow = (u32)(lane & 15);
    u32 lmk = (u32)((lane >> 4) << 3);

    for (int kc = 0; kc < 4; kc++) {
        int k0 = kc * 64;
        for (int i = tid; i < 4096; i += 256) {
            int r = i >> 5, kp = i & 31;
            size_t gsrc = ((size_t)tb * 128 + r) * 128 + (k0 >> 1) + kp;
            Ah32[r * 36 + kp] = g_A2h[gsrc];
            Al32[r * 36 + kp] = g_A2l[gsrc];
        }
        for (int i = tid; i < 3072; i += 256) {
            int n = i >> 5, kp = i & 31;
            size_t gsrc = (size_t)(col0 + n) * 128 + (k0 >> 1) + kp;
            Bh32[n * 36 + kp] = gB2h[gsrc];
            Bl32[n * 36 + kp] = gB2l[gsrc];
        }
        __syncthreads();
#pragma unroll
        for (int ks = 0; ks < 4; ks++) {
            u32 kk = (u32)(ks * 16);
            u32 a_h[2][4], a_l[2][4];
#pragma unroll
            for (int mt = 0; mt < 2; mt++) {
                u32 ad = sbase + (((u32)(wr + mt * 16) + lmrow) * 72 + kk + lmk) * 2;
                ldmx4(a_h[mt][0], a_h[mt][1], a_h[mt][2], a_h[mt][3], ad);
                ldmx4(a_l[mt][0], a_l[mt][1], a_l[mt][2], a_l[mt][3], ad + 18432);
            }
            u32 b_h[6][2], b_l[6][2];
#pragma unroll
            for (int np = 0; np < 3; np++) {
                u32 bd = sbase + 36864 +
                         (((u32)(wc + np * 16) + lmrow) * 72 + kk + lmk) * 2;
                u32 r0, r1, r2, r3;
                ldmx4(r0, r1, r2, r3, bd);
                b_h[np * 2][0] = r0; b_h[np * 2][1] = r2;
                b_h[np * 2 + 1][0] = r1; b_h[np * 2 + 1][1] = r3;
                ldmx4(r0, r1, r2, r3, bd + 13824);
                b_l[np * 2][0] = r0; b_l[np * 2][1] = r2;
                b_l[np * 2 + 1][0] = r1; b_l[np * 2 + 1][1] = r3;
            }
#pragma unroll
            for (int mt = 0; mt < 2; mt++)
#pragma unroll
                for (int nt = 0; nt < 6; nt++) {
                    mma_bf16(acc[mt][nt], a_h[mt], b_h[nt]);
                    mma_bf16(acc[mt][nt], a_l[mt], b_h[nt]);
                    mma_bf16(acc[mt][nt], a_h[mt], b_l[nt]);
                }
        }
        __syncthreads();
    }
    // stage P into smem
#pragma unroll
    for (int mt = 0; mt < 2; mt++) {
        int r = wr + mt * 16 + (lane >> 2);
#pragma unroll
        for (int nt = 0; nt < 6; nt++) {
            int col = wc + nt * 8 + (lane & 3) * 2;
            float bb0 = g_ob2perm[col0 + col];
            float bb1 = g_ob2perm[col0 + col + 1];
            Ps[r * 100 + col] = acc[mt][nt][0] + bb0;
            Ps[r * 100 + col + 1] = acc[mt][nt][1] + bb1;
            Ps[(r + 8) * 100 + col] = acc[mt][nt][2] + bb0;
            Ps[(r + 8) * 100 + col + 1] = acc[mt][nt][3] + bb1;
        }
    }
    __syncthreads();
    // emission partial: 2 threads per state
    {
        int n = tid >> 1;
        int hh = tid & 1;
        int nd = nh ? 32 : 48;
        int d0 = nh ? 48 : 0;
        float em = 0.f;
        int j0 = hh * (nd >> 1), j1 = j0 + (nd >> 1);
        for (int j = j0; j < j1; j++) {
            float mean = Ps[n * 100 + 2 * j];
            float sh = Ps[n * 100 + 2 * j + 1];
            float sp = (sh > 15.f) ? sh : __logf(1.f + __expf(sh));
            float stdv = sp + 0.001f;
            float z = (xt[d0 + j] - mean) / stdv;
            em += -0.5f * z * z - __logf(stdv);
        }
        em += __shfl_xor_sync(0xffffffffu, em, 1);
        if (hh == 0) {
            if (nh == 0) {
                g_EMa[tb * 128 + n] = em;
            } else {
                g_EMb[tb * 128 + n] = em;
                float tv = Ps[n * 100 + 64];
                float s_move = 1.f / (1.f + __expf(-tv));
                float s_stay = 1.f - s_move;
                g_LS[tb * 128 + n] = __logf(fmaxf(s_stay, EPSC));
                g_LM[tb * 128 + n] = __logf(fmaxf(s_move, EPSC));
            }
        }
    }
}

// ---------------- alpha recursion ----------------
__global__ __launch_bounds__(256) void k_alpha(float* __restrict__ out,
                                               const int* __restrict__ inputs_len,
                                               const int* __restrict__ mel_lens) {
    int tid = threadIdx.x;
    int b = tid >> 5, l = tid & 31;
    int ilen = inputs_len[b], mlen = mel_lens[b];
    float la[4];
    float lp = 0.f;
    bool mk[4];
#pragma unroll
    for (int j = 0; j < 4; j++) mk[j] = (l * 4 + j) < ilen;
    for (int t = 0; t < Tt; t++) {
        int base = ((t << 3) + b) * 128 + l * 4;
        float4 ea4 = *(const float4*)&g_EMa[base];
        float4 eb4 = *(const float4*)&g_EMb[base];
        float era[4] = {ea4.x + eb4.x, ea4.y + eb4.y, ea4.z + eb4.z, ea4.w + eb4.w};
        float em[4];
#pragma unroll
        for (int j = 0; j < 4; j++)
            em[j] = mk[j] ? (era[j] - 40.f * LOG2PI) : 0.f;
        float v[4];
        if (t == 0) {
#pragma unroll
            for (int j = 0; j < 4; j++)
                v[j] = ((l == 0 && j == 0) ? 0.f : NEGV) + em[j];
        } else {
            float4 ls4 = *(const float4*)&g_LS[base];
            float4 lm4 = *(const float4*)&g_LM[base];
            float lau = __shfl_up_sync(0xffffffffu, la[3], 1);
            float lmu = __shfl_up_sync(0xffffffffu, lm4.w, 1);
            float lam1[4] = {lau, la[0], la[1], la[2]};
            float lmm1[4] = {lmu, lm4.x, lm4.y, lm4.z};
            float ls[4] = {ls4.x, ls4.y, ls4.z, ls4.w};
#pragma unroll
            for (int j = 0; j < 4; j++) {
                float stay = la[j] + ls[j];
                float leave = (l == 0 && j == 0) ? NEGV : lam1[j] + lmm1[j];
                float mx = fmaxf(stay, leave), mn = fminf(stay, leave);
                float ladd = mx + __logf(1.f + __expf(mn - mx));
                v[j] = em[j] + (mk[j] ? ladd : NEGV);
            }
        }
        float m = fmaxf(fmaxf(v[0], v[1]), fmaxf(v[2], v[3]));
#pragma unroll
        for (int off = 16; off; off >>= 1)
            m = fmaxf(m, __shfl_xor_sync(0xffffffffu, m, off));
        float s = __expf(v[0] - m) + __expf(v[1] - m) +
                  __expf(v[2] - m) + __expf(v[3] - m);
#pragma unroll
        for (int off = 16; off; off >>= 1)
            s += __shfl_xor_sync(0xffffffffu, s, off);
        float logc = m + __logf(s);
#pragma unroll
        for (int j = 0; j < 4; j++) la[j] = v[j] - logc;
        *(float4*)&out[8 + ((b << 8) + t) * 128 + l * 4] =
            make_float4(la[0], la[1], la[2], la[3]);
        if (l == 0 && t < mlen) lp += logc;
    }
    if (l == 0) out[b] = lp;
}

// ---------------- launch ----------------
extern "C" void kernel_launch(void* const* d_in, const int* in_sizes, int n_in,
                              void* d_out, int out_size) {
    const float* inputs = (const float*)d_in[0];
    const float* mels = (const float*)d_in[1];
    const float* w0 = (const float*)d_in[2];
    const float* w1p = (const float*)d_in[3];
    const float* wih = (const float*)d_in[4];
    const float* whh = (const float*)d_in[5];
    const float* bih = (const float*)d_in[6];
    const float* bhh = (const float*)d_in[7];
    const float* ow0 = (const float*)d_in[8];
    const float* ob0 = (const float*)d_in[9];
    const float* ow1 = (const float*)d_in[10];
    const float* ob1 = (const float*)d_in[11];
    const float* ow2 = (const float*)d_in[12];
    const float* ob2 = (const float*)d_in[13];
    const int* inputs_len = (const int*)d_in[14];
    const int* mel_lens = (const int*)d_in[15];
    float* out = (float*)d_out;

    cudaFuncSetAttribute(k_lstm, cudaFuncAttributeMaxDynamicSharedMemorySize,
                         LSTM_SMEMF * 4);
    cudaFuncSetAttribute(k_g2mma, cudaFuncAttributeMaxDynamicSharedMemorySize,
                         G2_SMEMB);
    cudaFuncSetAttribute(k_g3mma, cudaFuncAttributeMaxDynamicSharedMemorySize,
                         G3_SMEMB);

    float* pre0;  cudaGetSymbolAddress((void**)&pre0, g_PRE0);
    float* pre;   cudaGetSymbolAddress((void**)&pre, g_PRE);
    float* gi;    cudaGetSymbolAddress((void**)&gi, g_GI);
    float* zi;    cudaGetSymbolAddress((void**)&zi, g_ZI);
    float* hh;    cudaGetSymbolAddress((void**)&hh, g_H);
    float* hpm;   cudaGetSymbolAddress((void**)&hpm, g_HP);
    float* arx;   cudaGetSymbolAddress((void**)&arx, g_ARX);
    float* w0t;   cudaGetSymbolAddress((void**)&w0t, g_W0T);
    float* w1pt;  cudaGetSymbolAddress((void**)&w1pt, g_W1PT);
    float* wiht;  cudaGetSymbolAddress((void**)&wiht, g_WIHT);
    float* ow0et; cudaGetSymbolAddress((void**)&ow0et, g_OW0ET);
    float* ow0mt; cudaGetSymbolAddress((void**)&ow0mt, g_OW0MT);
    float* bsum;  cudaGetSymbolAddress((void**)&bsum, g_bsum);

    k_prep<<<256, 256>>>(w0, w1p, wih, ow0, ow1, ow2, ob2, bih, bhh, mels);
    k_gemm<1><<<dim3(2, 32), 256>>>(pre0, arx, w0t, nullptr, 2048, 256, 96);
    k_gemm<1><<<dim3(2, 32), 256>>>(pre, pre0, w1pt, nullptr, 2048, 256, 256);
    k_gemm<0><<<dim3(16, 32), 256>>>(gi, pre, wiht, bsum, 2048, 2048, 256);
    k_gemm<0><<<dim3(2, 16), 256>>>(zi, inputs, ow0et, nullptr, 1024, 256, 512);
    k_lstm<<<64, 256, LSTM_SMEMF * 4>>>(whh);
    k_gemm<0><<<dim3(2, 32), 256>>>(hpm, hh, ow0mt, ob0, 2048, 256, 512);
    k_g2mma<<<dim3(2, 2048), 256, G2_SMEMB>>>(ob1);
    k_g3mma<<<dim3(2, 2048), 256, G3_SMEMB>>>(mels, inputs_len);
    k_alpha<<<1, 256>>>(out, inputs_len, mel_lens);
    (void)in_sizes; (void)n_in; (void)out_size;
}